// round 10
// baseline (speedup 1.0000x reference)
#include <cuda_runtime.h>
#include <cstdint>

// Problem constants
#define B_TOT   4096
#define S_DIM   64
#define H_DIM   64
#define N_SEL   4
#define ATT_DIM 128
#define P_DIM   64

#define G_PER_BLK 2
#define NBLKS (B_TOT / G_PER_BLK)        // 2048
#define THREADS 512
#define PITCH 68                          // smem row pitch (floats)

// Output layout (flatten-concat, float32):
#define OFF_RES  1048576u
#define OFF_LOSS 2097152u
#define OFF_IDX  2097153u

// Scratch (no allocations allowed -> device globals)
// M_t layout: g_M[(n*64 + k)*64 + h]  (k-major rows, h contiguous -> coalesced)
__device__ __align__(16) float g_M[N_SEL * H_DIM * H_DIM];
__device__ __align__(16) float g_pe[S_DIM * H_DIM];
__device__ __align__(16) float g_pesum[H_DIM];     // sum_s pe[s][h]
__device__ float g_partial[NBLKS];
__device__ unsigned int g_count;          // zero-init; last block resets -> replay-safe

// ---------------------------------------------------------------------------
// Fused prep: blocks [0,256): M_t[n][k][h] = sum_a Wq[n,a,h]*Wk[n,a,k]
//             blocks [256,260): positional encoding (numpy-f32 rounding)
//             block 260: pe column sums (recomputes pe values; no cross-block dep)
// ---------------------------------------------------------------------------
__global__ void prep_kernel(const float* __restrict__ Wq, const float* __restrict__ Wk) {
    const float c = (float)(-0.14391156056944368);   // f32(-ln(1e4)/64)
    if (blockIdx.x < 256) {
        int nk = blockIdx.x;
        int h  = threadIdx.x;
        int n  = nk >> 6;
        int k  = nk & 63;
        const float* wq = Wq + (size_t)n * ATT_DIM * H_DIM + h;   // lane-coalesced
        const float* wk = Wk + (size_t)n * ATT_DIM * H_DIM + k;   // broadcast
        float acc = 0.f;
#pragma unroll 8
        for (int a = 0; a < ATT_DIM; ++a)
            acc += wq[a * H_DIM] * wk[a * H_DIM];
        g_M[nk * 64 + h] = acc;           // [(n*64+k)*64 + h]
    } else if (blockIdx.x < 260) {
        int base = (blockIdx.x - 256) * 1024;
#pragma unroll
        for (int k = 0; k < 16; ++k) {
            int idx = base + k * 64 + threadIdx.x;
            int s = idx >> 6, h = idx & 63;
            float arg  = (float)(h & ~1) * c;
            float divf = (float)exp((double)arg);
            float ang  = (float)s * divf;
            double sv  = (h & 1) ? cos((double)ang) : sin((double)ang);
            g_pe[idx] = (float)sv;
        }
    } else {
        int h = threadIdx.x;              // 64 threads
        float arg  = (float)(h & ~1) * c;
        float divf = (float)exp((double)arg);
        float acc = 0.f;
        for (int s = 0; s < S_DIM; ++s) {
            float ang = (float)s * divf;
            double sv = (h & 1) ? cos((double)ang) : sin((double)ang);
            acc += (float)sv;             // f32 accumulate, s ascending
        }
        g_pesum[h] = acc;
    }
}

// ---------------------------------------------------------------------------
// threefry2x32, JAX partitionable mode: counter -> (0, gi), key (0,1),
// 32-bit draw = out0 ^ out1; uniform -> gumbel (bit-fidelity is load-bearing)
// ---------------------------------------------------------------------------
__device__ __forceinline__ uint32_t rotl32(uint32_t x, int d) {
    return (x << d) | (x >> (32 - d));
}

__device__ __forceinline__ float gumbel_at(uint32_t gi) {
    const uint32_t k0 = 0u, k1 = 1u, k2 = 0x1BD11BDBu;
    uint32_t x0 = 0u + k0;
    uint32_t x1 = gi + k1;
#define TF_ROUND(r) { x0 += x1; x1 = rotl32(x1, (r)); x1 ^= x0; }
    TF_ROUND(13) TF_ROUND(15) TF_ROUND(26) TF_ROUND(6)
    x0 += k1; x1 += k2 + 1u;
    TF_ROUND(17) TF_ROUND(29) TF_ROUND(16) TF_ROUND(24)
    x0 += k2; x1 += k0 + 2u;
    TF_ROUND(13) TF_ROUND(15) TF_ROUND(26) TF_ROUND(6)
    x0 += k0; x1 += k1 + 3u;
    TF_ROUND(17) TF_ROUND(29) TF_ROUND(16) TF_ROUND(24)
    x0 += k1; x1 += k2 + 4u;
    TF_ROUND(13) TF_ROUND(15) TF_ROUND(26) TF_ROUND(6)
    x0 += k2; x1 += k0 + 5u;
#undef TF_ROUND
    uint32_t bits = x0 ^ x1;
    uint32_t fb = (bits >> 9) | 0x3f800000u;
    float u = __uint_as_float(fb) - 1.0f;
    u = fmaxf(u, 1.17549435e-38f);
    return -logf(-logf(u));
}

// ---------------------------------------------------------------------------
// Main fused kernel: 2048 blocks x 512 threads, 2 batches per block,
// 2 CTAs co-resident per SM. No xs staging: pos recomputed from L1-hot
// global x + pe in the score phase; psum read directly from global.
// ---------------------------------------------------------------------------
#define PROS_F  (P_DIM * PITCH)                  // 4352
#define VS_F    (8 * PITCH)                      // 544
#define PART_F  1024
#define SMEM_FLOATS (PROS_F + VS_F + 128 + PART_F + 8*PITCH + 64 + 64 + 24)
#define SMEM_BYTES  (SMEM_FLOATS * 4)

__global__ void __launch_bounds__(THREADS, 2) main_kernel(
    const float* __restrict__ x,
    const float* __restrict__ prototypes,
    float* __restrict__ out)
{
    extern __shared__ float sm[];
    float* pros  = sm;                       // [p][PITCH]
    float* vs    = pros + PROS_F;            // [(g*4+n)][PITCH]   8 rows
    float* psumb = vs + VS_F;                // [g][64]            128
    float* part  = psumb + 128;              // [1024] partials / reductions
    float* xsel  = part + PART_F;            // [(g*4+n)][PITCH]   8 rows
    float* candv = xsel + 8 * PITCH;         // [64]  (16 warps x 4)
    int*   candi = (int*)(candv + 64);       // [64]
    int*   isel  = candi + 64;               // [8]
    int*   psel  = isel + 8;                 // [8]
    __shared__ unsigned int amLast;

    const int tid  = threadIdx.x;
    const int lane = tid & 31;
    const int w    = tid >> 5;
    const int b0   = blockIdx.x * G_PER_BLK;

    // coords for (g, n, h)-style phases
    const int cg = tid >> 8;          // 0..1
    const int cn = (tid >> 6) & 3;    // 0..3
    const int ch = tid & 63;          // 0..63
    // coords for score/d2 phases (n minor -> 4-way multicast / coalesced dedup)
    const int sg = tid >> 8;          // 0..1
    const int sp = (tid >> 2) & 63;   // s (score) or p (VQ)
    const int sn = tid & 3;

    // --- stage prototypes: 1024 float4 over 512 threads ---
    {
        const float4* pp4 = reinterpret_cast<const float4*>(prototypes);
#pragma unroll
        for (int j = 0; j < 2; ++j) {
            int i4 = j * 512 + tid;
            int p  = i4 >> 4;
            int k4 = i4 & 15;
            *reinterpret_cast<float4*>(&pros[p * PITCH + k4 * 4]) = pp4[i4];
        }
    }

    // one gumbel per thread, matching score-phase (g,n,s) coordinates
    // (long ALU chain; scheduler interleaves with the psum LDG stream below)
    float gnoise = gumbel_at((uint32_t)(b0 + sg) * 256u + (uint32_t)sn * 64u + (uint32_t)sp);

    // --- psum partials directly from global x: thread (g, q, h) sums 16 s ---
    {
        int q = (tid >> 6) & 3;
        const float* xg = x + ((size_t)(b0 + cg) * S_DIM + q * 16) * H_DIM + ch;
        float ps = 0.f;
#pragma unroll
        for (int s16 = 0; s16 < 16; ++s16)
            ps += xg[s16 * 64];
        part[tid] = ps;                 // [(g*4+q)*64 + h] == tid
    }
    __syncthreads();
    if (tid < 128) {
        int g = tid >> 6, h = tid & 63;
        psumb[tid] = (part[g * 256 + h] + part[g * 256 + 64 + h]
                    + part[g * 256 + 128 + h] + part[g * 256 + 192 + h])
                   + g_pesum[h];
    }
    __syncthreads();

    // --- v partials: thread (n, k-half, h); M loaded ONCE per block,
    //     both groups accumulated against float4-broadcast psum reads ---
    {
        const int vn = tid >> 7;          // 0..3
        const int vq = (tid >> 6) & 1;    // k-half
        const int vh = tid & 63;
        const float* Mt = g_M + ((size_t)(vn * 64 + vq * 32) * 64 + vh);
        float a0 = 0.f, a1 = 0.f;
#pragma unroll
        for (int j = 0; j < 8; ++j) {
            float m0 = Mt[(j * 4 + 0) * 64];
            float m1 = Mt[(j * 4 + 1) * 64];
            float m2 = Mt[(j * 4 + 2) * 64];
            float m3 = Mt[(j * 4 + 3) * 64];
            float4 p0 = *reinterpret_cast<const float4*>(&psumb[ 0 + vq * 32 + j * 4]);
            float4 p1 = *reinterpret_cast<const float4*>(&psumb[64 + vq * 32 + j * 4]);
            a0 += m0 * p0.x + m1 * p0.y + m2 * p0.z + m3 * p0.w;
            a1 += m0 * p1.x + m1 * p1.y + m2 * p1.z + m3 * p1.w;
        }
        int base = vq * 512 + vn * 64 + vh;
        part[base +   0] = a0;            // [vq][(g*4+n)*64 + h], g=0..1
        part[base + 256] = a1;
    }
    __syncthreads();
    // --- combine k-halves: tid == (g*4+n)*64 + h ---
    {
        float v = part[tid] + part[512 + tid];
        vs[(cg * 4 + cn) * PITCH + ch] = v * (1.0f / 512.0f);
    }
    __syncthreads();

    // --- score[g][n][s] = (x[s]+pe[s]) . v[g][n] + gumbel ---
    //     x row is L1-hot (streamed by psum above); pe is L1/L2-hot globally.
    float myscore;
    {
        const float4* xr4 = reinterpret_cast<const float4*>(
            x + ((size_t)(b0 + sg) * S_DIM + sp) * H_DIM);
        const float4* pe4 = reinterpret_cast<const float4*>(g_pe + sp * H_DIM);
        const float4* vr4 = reinterpret_cast<const float4*>(&vs[(sg * 4 + sn) * PITCH]);
        float lg = 0.f;
#pragma unroll
        for (int h4 = 0; h4 < 16; ++h4) {
            float4 a = xr4[h4], p = pe4[h4], b = vr4[h4];
            lg += (a.x + p.x) * b.x + (a.y + p.y) * b.y
                + (a.z + p.z) * b.z + (a.w + p.w) * b.w;
        }
        myscore = lg + gnoise;
    }
    // argmax over s within warp (8 s-values per warp; lane = s_local*4 + n)
    {
        float v = myscore; int idx = sp;
#pragma unroll
        for (int off = 4; off <= 16; off <<= 1) {
            float ov = __shfl_xor_sync(0xFFFFFFFFu, v, off);
            int   oi = __shfl_xor_sync(0xFFFFFFFFu, idx, off);
            if (ov > v || (ov == v && oi < idx)) { v = ov; idx = oi; }
        }
        if (lane < 4) { candv[w * 4 + lane] = v; candi[w * 4 + lane] = idx; }
    }
    __syncthreads();
    if (tid < 8) {      // combine 8 warps per (g,n), first-max
        int g = tid >> 2, n = tid & 3;
        float best = candv[(g * 8) * 4 + n];
        int   bi   = candi[(g * 8) * 4 + n];
        for (int wb = 1; wb < 8; ++wb) {
            float v = candv[(g * 8 + wb) * 4 + n];
            int   i = candi[(g * 8 + wb) * 4 + n];
            if (v > best || (v == best && i < bi)) { best = v; bi = i; }
        }
        isel[tid] = bi;
        out[OFF_IDX + (size_t)(b0 + g) * N_SEL + n] = (float)bi;
    }
    __syncthreads();

    // --- gather selected raw x rows ---
    xsel[(cg * 4 + cn) * PITCH + ch] =
        x[((size_t)(b0 + cg) * S_DIM + isel[cg * 4 + cn]) * H_DIM + ch];
    __syncthreads();

    // --- VQ relative distance d[g][n][p] = pros[p].(pros[p] - 2*xsel[g][n]) ---
    float myd;
    {
        const float4* prow4 = reinterpret_cast<const float4*>(&pros[sp * PITCH]);
        const float4* xr4   = reinterpret_cast<const float4*>(&xsel[(sg * 4 + sn) * PITCH]);
        float d = 0.f;
#pragma unroll
        for (int k4 = 0; k4 < 16; ++k4) {
            float4 pv = prow4[k4], xv = xr4[k4];
            d += pv.x * (pv.x - 2.0f * xv.x);
            d += pv.y * (pv.y - 2.0f * xv.y);
            d += pv.z * (pv.z - 2.0f * xv.z);
            d += pv.w * (pv.w - 2.0f * xv.w);
        }
        myd = d;
    }
    {
        float v = myd; int idx = sp;
#pragma unroll
        for (int off = 4; off <= 16; off <<= 1) {
            float ov = __shfl_xor_sync(0xFFFFFFFFu, v, off);
            int   oi = __shfl_xor_sync(0xFFFFFFFFu, idx, off);
            if (ov < v || (ov == v && oi < idx)) { v = ov; idx = oi; }
        }
        if (lane < 4) { candv[w * 4 + lane] = v; candi[w * 4 + lane] = idx; }
    }
    __syncthreads();
    if (tid < 8) {      // combine, first-min
        int g = tid >> 2, n = tid & 3;
        float best = candv[(g * 8) * 4 + n];
        int   bi   = candi[(g * 8) * 4 + n];
        for (int wb = 1; wb < 8; ++wb) {
            float v = candv[(g * 8 + wb) * 4 + n];
            int   i = candi[(g * 8 + wb) * 4 + n];
            if (v < best || (v == best && i < bi)) { best = v; bi = i; }
        }
        psel[tid] = bi;
    }
    __syncthreads();

    // --- outputs (reference rounding preserved) + loss contribution ---
    float losspart;
    {
        float xv  = xsel[(cg * 4 + cn) * PITCH + ch];
        float pv  = pros[psel[cg * 4 + cn] * PITCH + ch];
        float d   = pv - xv;
        float pst = xv + d;
        size_t ob = (size_t)(b0 + cg) * 256 + (size_t)(tid & 255);
        out[ob]           = pst;
        out[OFF_RES + ob] = xv - pst;
        losspart = d * d;
    }

    // --- deterministic loss reduction (warp shuffle + smem combine) ---
    {
        float v = losspart;
#pragma unroll
        for (int off = 16; off > 0; off >>= 1)
            v += __shfl_xor_sync(0xFFFFFFFFu, v, off);
        if (lane == 0) part[w] = v;
    }
    __syncthreads();
    if (tid < 32) {
        float v = (tid < 16) ? part[tid] : 0.f;
#pragma unroll
        for (int off = 16; off > 0; off >>= 1)
            v += __shfl_xor_sync(0xFFFFFFFFu, v, off);
        if (tid == 0) g_partial[blockIdx.x] = v;
    }

    // --- fused loss finalize: last block sums 2048 partials ---
    __threadfence();
    if (tid == 0)
        amLast = (atomicAdd(&g_count, 1u) == (unsigned)(NBLKS - 1)) ? 1u : 0u;
    __syncthreads();
    if (amLast) {
        __threadfence();
        float v = g_partial[tid] + g_partial[512 + tid]
                + g_partial[1024 + tid] + g_partial[1536 + tid];
#pragma unroll
        for (int off = 16; off > 0; off >>= 1)
            v += __shfl_xor_sync(0xFFFFFFFFu, v, off);
        if (lane == 0) part[w] = v;
        __syncthreads();
        if (tid < 32) {
            float s = (tid < 16) ? part[tid] : 0.f;
#pragma unroll
            for (int off = 16; off > 0; off >>= 1)
                s += __shfl_xor_sync(0xFFFFFFFFu, s, off);
            if (tid == 0) {
                out[OFF_LOSS] = s * 1.25f / (float)(B_TOT * N_SEL * H_DIM);
                g_count = 0;            // reset for next graph replay
            }
        }
    }
}

// ---------------------------------------------------------------------------
extern "C" void kernel_launch(void* const* d_in, const int* in_sizes, int n_in,
                              void* d_out, int out_size) {
    (void)in_sizes; (void)n_in; (void)out_size;
    const float* x  = (const float*)d_in[0];
    const float* Wq = (const float*)d_in[1];
    const float* Wk = (const float*)d_in[2];
    const float* pr = (const float*)d_in[3];
    float* out = (float*)d_out;

    cudaFuncSetAttribute(main_kernel,
                         cudaFuncAttributeMaxDynamicSharedMemorySize, SMEM_BYTES);

    prep_kernel<<<261, 64>>>(Wq, Wk);
    main_kernel<<<NBLKS, THREADS, SMEM_BYTES>>>(x, pr, out);
}

// round 11
// speedup vs baseline: 1.4459x; 1.4459x over previous
#include <cuda_runtime.h>
#include <cstdint>

// Problem constants
#define B_TOT   4096
#define S_DIM   64
#define H_DIM   64
#define N_SEL   4
#define ATT_DIM 128
#define P_DIM   64

#define NBLKS   B_TOT                    // 4096 blocks, 1 batch each
#define THREADS 256
#define PITCH 68                          // smem row pitch (floats)

// Output layout (flatten-concat, float32):
#define OFF_RES  1048576u
#define OFF_LOSS 2097152u
#define OFF_IDX  2097153u

// Scratch (no allocations allowed -> device globals)
// M_t layout: g_M[(n*64 + k)*64 + h]  (k-major rows, h contiguous -> coalesced)
__device__ __align__(16) float g_M[N_SEL * H_DIM * H_DIM];
__device__ __align__(16) float g_pe[S_DIM * H_DIM];
__device__ float g_partial[NBLKS];
__device__ unsigned int g_count;          // zero-init; last block resets -> replay-safe

// ---------------------------------------------------------------------------
// Fused prep: blocks [0,256): M_t[n][k][h] = sum_a Wq[n,a,h]*Wk[n,a,k]
//             blocks [256,260): positional encoding (numpy-f32 rounding)
// ---------------------------------------------------------------------------
__global__ void prep_kernel(const float* __restrict__ Wq, const float* __restrict__ Wk) {
    const float c = (float)(-0.14391156056944368);   // f32(-ln(1e4)/64)
    if (blockIdx.x < 256) {
        int nk = blockIdx.x;
        int h  = threadIdx.x;
        int n  = nk >> 6;
        int k  = nk & 63;
        const float* wq = Wq + (size_t)n * ATT_DIM * H_DIM + h;   // lane-coalesced
        const float* wk = Wk + (size_t)n * ATT_DIM * H_DIM + k;   // broadcast
        float acc = 0.f;
#pragma unroll 8
        for (int a = 0; a < ATT_DIM; ++a)
            acc += wq[a * H_DIM] * wk[a * H_DIM];
        g_M[nk * 64 + h] = acc;           // [(n*64+k)*64 + h]
    } else {
        int base = (blockIdx.x - 256) * 1024;
#pragma unroll
        for (int k = 0; k < 16; ++k) {
            int idx = base + k * 64 + threadIdx.x;
            int s = idx >> 6, h = idx & 63;
            float arg  = (float)(h & ~1) * c;
            float divf = (float)exp((double)arg);
            float ang  = (float)s * divf;
            double sv  = (h & 1) ? cos((double)ang) : sin((double)ang);
            g_pe[idx] = (float)sv;
        }
    }
}

// ---------------------------------------------------------------------------
// threefry2x32, JAX partitionable mode: counter -> (0, gi), key (0,1),
// 32-bit draw = out0 ^ out1; uniform -> gumbel (bit-fidelity is load-bearing)
// ---------------------------------------------------------------------------
__device__ __forceinline__ uint32_t rotl32(uint32_t x, int d) {
    return (x << d) | (x >> (32 - d));
}

__device__ __forceinline__ float gumbel_at(uint32_t gi) {
    const uint32_t k0 = 0u, k1 = 1u, k2 = 0x1BD11BDBu;
    uint32_t x0 = 0u + k0;
    uint32_t x1 = gi + k1;
#define TF_ROUND(r) { x0 += x1; x1 = rotl32(x1, (r)); x1 ^= x0; }
    TF_ROUND(13) TF_ROUND(15) TF_ROUND(26) TF_ROUND(6)
    x0 += k1; x1 += k2 + 1u;
    TF_ROUND(17) TF_ROUND(29) TF_ROUND(16) TF_ROUND(24)
    x0 += k2; x1 += k0 + 2u;
    TF_ROUND(13) TF_ROUND(15) TF_ROUND(26) TF_ROUND(6)
    x0 += k0; x1 += k1 + 3u;
    TF_ROUND(17) TF_ROUND(29) TF_ROUND(16) TF_ROUND(24)
    x0 += k1; x1 += k2 + 4u;
    TF_ROUND(13) TF_ROUND(15) TF_ROUND(26) TF_ROUND(6)
    x0 += k2; x1 += k0 + 5u;
#undef TF_ROUND
    uint32_t bits = x0 ^ x1;
    uint32_t fb = (bits >> 9) | 0x3f800000u;
    float u = __uint_as_float(fb) - 1.0f;
    u = fmaxf(u, 1.17549435e-38f);
    return -logf(-logf(u));
}

// ---------------------------------------------------------------------------
// Main fused kernel: 4096 blocks x 256 threads, ONE batch per block,
// 4 CTAs co-resident per SM (RF-exact: 256*64*4 = 64K regs) so four
// independent phase chains overlap each other's barrier drains.
// ---------------------------------------------------------------------------
#define XS_F    (S_DIM * PITCH)                  // 4352
#define PROS_F  (P_DIM * PITCH)                  // 4352
#define VS_F    (N_SEL * PITCH)                  // 272
#define SMEM_FLOATS (XS_F + PROS_F + VS_F + 64 + 256 + N_SEL*PITCH + 32 + 32 + 16)
#define SMEM_BYTES  (SMEM_FLOATS * 4)

__global__ void __launch_bounds__(THREADS, 4) main_kernel(
    const float* __restrict__ x,
    const float* __restrict__ prototypes,
    float* __restrict__ out)
{
    extern __shared__ float sm[];
    float* xs    = sm;                       // [s][PITCH]
    float* pros  = xs + XS_F;                // [p][PITCH]
    float* vs    = pros + PROS_F;            // [n][PITCH]
    float* psumb = vs + VS_F;                // [64]
    float* part  = psumb + 64;               // [256] partials / reductions
    float* xsel  = part + 256;               // [n][PITCH]
    float* candv = xsel + N_SEL * PITCH;     // [32]  (8 warps x 4)
    int*   candi = (int*)(candv + 32);       // [32]
    int*   isel  = candi + 32;               // [4]
    int*   psel  = isel + 4;                 // [4]
    __shared__ unsigned int amLast;

    const int tid  = threadIdx.x;
    const int lane = tid & 31;
    const int w    = tid >> 5;
    const int b    = blockIdx.x;

    // coords for (n, h)-style phases
    const int cn = tid >> 6;          // 0..3
    const int ch = tid & 63;          // 0..63
    // coords for score/d2 phases (n minor -> 4-way row multicast)
    const int sp = tid >> 2;          // s (score) or p (VQ), 0..63
    const int sn = tid & 3;

    // --- stage prototypes: 1024 float4 over 256 threads ---
    {
        const float4* pp4 = reinterpret_cast<const float4*>(prototypes);
#pragma unroll
        for (int j = 0; j < 4; ++j) {
            int i4 = j * 256 + tid;
            int p  = i4 >> 4;
            int k4 = i4 & 15;
            *reinterpret_cast<float4*>(&pros[p * PITCH + k4 * 4]) = pp4[i4];
        }
    }
    // --- stage pos = x + pe: 1024 float4 ---
    {
        const float4* xb4 = reinterpret_cast<const float4*>(x + (size_t)b * S_DIM * H_DIM);
        const float4* pe4 = reinterpret_cast<const float4*>(g_pe);
#pragma unroll
        for (int j = 0; j < 4; ++j) {
            int i4 = j * 256 + tid;
            int s  = i4 >> 4;
            int h4 = i4 & 15;
            float4 xv = xb4[i4];
            float4 pv = pe4[i4];
            float4 o;
            o.x = xv.x + pv.x; o.y = xv.y + pv.y;
            o.z = xv.z + pv.z; o.w = xv.w + pv.w;
            *reinterpret_cast<float4*>(&xs[s * PITCH + h4 * 4]) = o;
        }
    }

    // one gumbel per thread, matching score-phase (n,s) coordinates
    // (long ALU chain; scheduler interleaves with the staging LDG stream)
    float gnoise = gumbel_at((uint32_t)b * 256u + (uint32_t)sn * 64u + (uint32_t)sp);

    __syncthreads();

    // --- psum partials: thread (q, h) sums 16 s-values ---
    {
        int q = tid >> 6;
        const float* base = &xs[(q * 16) * PITCH + ch];
        float ps = 0.f;
#pragma unroll
        for (int s16 = 0; s16 < 16; ++s16)
            ps += base[s16 * PITCH];
        part[tid] = ps;                 // [q*64 + h] == tid
    }
    __syncthreads();
    if (tid < 64) {
        psumb[tid] = part[tid] + part[64 + tid] + part[128 + tid] + part[192 + tid];
    }
    __syncthreads();

    // --- v[n][h] = (M_t[n][:,h] . psum) / 512 : thread (n,h), coalesced M ---
    {
        const float* Mt = g_M + ((size_t)cn * 64) * 64 + ch;   // stride 64 per k
        float a = 0.f;
#pragma unroll
        for (int j = 0; j < 16; ++j) {
            float m0 = Mt[(j * 4 + 0) * 64];
            float m1 = Mt[(j * 4 + 1) * 64];
            float m2 = Mt[(j * 4 + 2) * 64];
            float m3 = Mt[(j * 4 + 3) * 64];
            float4 p = *reinterpret_cast<const float4*>(&psumb[j * 4]);
            a += m0 * p.x + m1 * p.y + m2 * p.z + m3 * p.w;
        }
        vs[cn * PITCH + ch] = a * (1.0f / 512.0f);
    }
    __syncthreads();

    // --- score[n][s] = pos[s] . v[n] + gumbel (xs row 4-way multicast) ---
    float myscore;
    {
        const float4* pr4 = reinterpret_cast<const float4*>(&xs[sp * PITCH]);
        const float4* vr4 = reinterpret_cast<const float4*>(&vs[sn * PITCH]);
        float lg = 0.f;
#pragma unroll
        for (int h4 = 0; h4 < 16; ++h4) {
            float4 a = pr4[h4], v = vr4[h4];
            lg += a.x * v.x + a.y * v.y + a.z * v.z + a.w * v.w;
        }
        myscore = lg + gnoise;
    }
    // argmax over s within warp (8 s-values per warp; lane = s_local*4 + n)
    {
        float v = myscore; int idx = sp;
#pragma unroll
        for (int off = 4; off <= 16; off <<= 1) {
            float ov = __shfl_xor_sync(0xFFFFFFFFu, v, off);
            int   oi = __shfl_xor_sync(0xFFFFFFFFu, idx, off);
            if (ov > v || (ov == v && oi < idx)) { v = ov; idx = oi; }
        }
        if (lane < 4) { candv[w * 4 + lane] = v; candi[w * 4 + lane] = idx; }
    }
    __syncthreads();
    if (tid < 4) {      // combine 8 warps per n, first-max (warps ascend in s)
        float best = candv[tid];
        int   bi   = candi[tid];
        for (int wb = 1; wb < 8; ++wb) {
            float v = candv[wb * 4 + tid];
            int   i = candi[wb * 4 + tid];
            if (v > best || (v == best && i < bi)) { best = v; bi = i; }
        }
        isel[tid] = bi;
        out[OFF_IDX + (size_t)b * N_SEL + tid] = (float)bi;
    }
    __syncthreads();

    // --- gather selected raw x rows ---
    xsel[cn * PITCH + ch] = x[((size_t)b * S_DIM + isel[cn]) * H_DIM + ch];
    __syncthreads();

    // --- VQ relative distance d[n][p] = pros[p].(pros[p] - 2*xsel[n]) ---
    float myd;
    {
        const float4* prow4 = reinterpret_cast<const float4*>(&pros[sp * PITCH]);
        const float4* xr4   = reinterpret_cast<const float4*>(&xsel[sn * PITCH]);
        float d = 0.f;
#pragma unroll
        for (int k4 = 0; k4 < 16; ++k4) {
            float4 pv = prow4[k4], xv = xr4[k4];
            d += pv.x * (pv.x - 2.0f * xv.x);
            d += pv.y * (pv.y - 2.0f * xv.y);
            d += pv.z * (pv.z - 2.0f * xv.z);
            d += pv.w * (pv.w - 2.0f * xv.w);
        }
        myd = d;
    }
    {
        float v = myd; int idx = sp;
#pragma unroll
        for (int off = 4; off <= 16; off <<= 1) {
            float ov = __shfl_xor_sync(0xFFFFFFFFu, v, off);
            int   oi = __shfl_xor_sync(0xFFFFFFFFu, idx, off);
            if (ov < v || (ov == v && oi < idx)) { v = ov; idx = oi; }
        }
        if (lane < 4) { candv[w * 4 + lane] = v; candi[w * 4 + lane] = idx; }
    }
    __syncthreads();
    if (tid < 4) {      // combine, first-min
        float best = candv[tid];
        int   bi   = candi[tid];
        for (int wb = 1; wb < 8; ++wb) {
            float v = candv[wb * 4 + tid];
            int   i = candi[wb * 4 + tid];
            if (v < best || (v == best && i < bi)) { best = v; bi = i; }
        }
        psel[tid] = bi;
    }
    __syncthreads();

    // --- outputs (reference rounding preserved) + loss contribution ---
    float losspart;
    {
        float xv  = xsel[cn * PITCH + ch];
        float pv  = pros[psel[cn] * PITCH + ch];
        float d   = pv - xv;
        float pst = xv + d;
        size_t ob = (size_t)b * 256 + (size_t)tid;
        out[ob]           = pst;
        out[OFF_RES + ob] = xv - pst;
        losspart = d * d;
    }

    // --- deterministic loss reduction (warp shuffle + smem combine) ---
    {
        float v = losspart;
#pragma unroll
        for (int off = 16; off > 0; off >>= 1)
            v += __shfl_xor_sync(0xFFFFFFFFu, v, off);
        if (lane == 0) part[w] = v;
    }
    __syncthreads();
    if (tid < 32) {
        float v = (tid < 8) ? part[tid] : 0.f;
#pragma unroll
        for (int off = 16; off > 0; off >>= 1)
            v += __shfl_xor_sync(0xFFFFFFFFu, v, off);
        if (tid == 0) g_partial[b] = v;
    }

    // --- fused loss finalize: last block sums 4096 partials in fixed order ---
    __threadfence();
    if (tid == 0)
        amLast = (atomicAdd(&g_count, 1u) == (unsigned)(NBLKS - 1)) ? 1u : 0u;
    __syncthreads();
    if (amLast) {
        __threadfence();
        float v = 0.f;
#pragma unroll
        for (int j = 0; j < 16; ++j)            // fixed order -> deterministic
            v += g_partial[j * 256 + tid];
#pragma unroll
        for (int off = 16; off > 0; off >>= 1)
            v += __shfl_xor_sync(0xFFFFFFFFu, v, off);
        if (lane == 0) part[w] = v;
        __syncthreads();
        if (tid < 32) {
            float s = (tid < 8) ? part[tid] : 0.f;
#pragma unroll
            for (int off = 16; off > 0; off >>= 1)
                s += __shfl_xor_sync(0xFFFFFFFFu, s, off);
            if (tid == 0) {
                out[OFF_LOSS] = s * 1.25f / (float)(B_TOT * N_SEL * H_DIM);
                g_count = 0;            // reset for next graph replay
            }
        }
    }
}

// ---------------------------------------------------------------------------
extern "C" void kernel_launch(void* const* d_in, const int* in_sizes, int n_in,
                              void* d_out, int out_size) {
    (void)in_sizes; (void)n_in; (void)out_size;
    const float* x  = (const float*)d_in[0];
    const float* Wq = (const float*)d_in[1];
    const float* Wk = (const float*)d_in[2];
    const float* pr = (const float*)d_in[3];
    float* out = (float*)d_out;

    cudaFuncSetAttribute(main_kernel,
                         cudaFuncAttributeMaxDynamicSharedMemorySize, SMEM_BYTES);

    prep_kernel<<<260, 64>>>(Wq, Wk);
    main_kernel<<<NBLKS, THREADS, SMEM_BYTES>>>(x, pr, out);
}

// round 12
// speedup vs baseline: 1.6815x; 1.1630x over previous
#include <cuda_runtime.h>
#include <cstdint>

// Problem constants
#define B_TOT   4096
#define S_DIM   64
#define H_DIM   64
#define N_SEL   4
#define ATT_DIM 128
#define P_DIM   64

#define G_PER_BLK 2
#define NBLKS (B_TOT / G_PER_BLK)        // 2048
#define THREADS 256
#define PITCH 68                          // smem row pitch (floats), 16B-aligned

// Output layout (flatten-concat, float32):
#define OFF_RES  1048576u
#define OFF_LOSS 2097152u
#define OFF_IDX  2097153u

// Scratch (no allocations allowed -> device globals)
// M_t layout: g_M[(n*64 + k)*64 + h]  (k-major rows, h contiguous -> coalesced)
__device__ __align__(16) float g_M[N_SEL * H_DIM * H_DIM];
__device__ __align__(16) float g_pe[S_DIM * H_DIM];
__device__ float g_partial[NBLKS];
__device__ unsigned int g_count;          // zero-init; last block resets -> replay-safe

// ---------------------------------------------------------------------------
// Fused prep: blocks [0,256): M_t[n][k][h] = sum_a Wq[n,a,h]*Wk[n,a,k]
//             blocks [256,260): positional encoding (numpy-f32 rounding)
// ---------------------------------------------------------------------------
__global__ void prep_kernel(const float* __restrict__ Wq, const float* __restrict__ Wk) {
    const float c = (float)(-0.14391156056944368);   // f32(-ln(1e4)/64)
    if (blockIdx.x < 256) {
        int nk = blockIdx.x;
        int h  = threadIdx.x;
        int n  = nk >> 6;
        int k  = nk & 63;
        const float* wq = Wq + (size_t)n * ATT_DIM * H_DIM + h;   // lane-coalesced
        const float* wk = Wk + (size_t)n * ATT_DIM * H_DIM + k;   // broadcast
        float acc = 0.f;
#pragma unroll 8
        for (int a = 0; a < ATT_DIM; ++a)
            acc += wq[a * H_DIM] * wk[a * H_DIM];
        g_M[nk * 64 + h] = acc;           // [(n*64+k)*64 + h]
    } else {
        int base = (blockIdx.x - 256) * 1024;
#pragma unroll
        for (int k = 0; k < 16; ++k) {
            int idx = base + k * 64 + threadIdx.x;
            int s = idx >> 6, h = idx & 63;
            float arg  = (float)(h & ~1) * c;
            float divf = (float)exp((double)arg);
            float ang  = (float)s * divf;
            double sv  = (h & 1) ? cos((double)ang) : sin((double)ang);
            g_pe[idx] = (float)sv;
        }
    }
}

// ---------------------------------------------------------------------------
// threefry2x32, JAX partitionable mode: counter -> (0, gi), key (0,1),
// 32-bit draw = out0 ^ out1; uniform -> gumbel (bit-fidelity is load-bearing)
// ---------------------------------------------------------------------------
__device__ __forceinline__ uint32_t rotl32(uint32_t x, int d) {
    return (x << d) | (x >> (32 - d));
}

__device__ __forceinline__ float gumbel_at(uint32_t gi) {
    const uint32_t k0 = 0u, k1 = 1u, k2 = 0x1BD11BDBu;
    uint32_t x0 = 0u + k0;
    uint32_t x1 = gi + k1;
#define TF_ROUND(r) { x0 += x1; x1 = rotl32(x1, (r)); x1 ^= x0; }
    TF_ROUND(13) TF_ROUND(15) TF_ROUND(26) TF_ROUND(6)
    x0 += k1; x1 += k2 + 1u;
    TF_ROUND(17) TF_ROUND(29) TF_ROUND(16) TF_ROUND(24)
    x0 += k2; x1 += k0 + 2u;
    TF_ROUND(13) TF_ROUND(15) TF_ROUND(26) TF_ROUND(6)
    x0 += k0; x1 += k1 + 3u;
    TF_ROUND(17) TF_ROUND(29) TF_ROUND(16) TF_ROUND(24)
    x0 += k1; x1 += k2 + 4u;
    TF_ROUND(13) TF_ROUND(15) TF_ROUND(26) TF_ROUND(6)
    x0 += k2; x1 += k0 + 5u;
#undef TF_ROUND
    uint32_t bits = x0 ^ x1;
    uint32_t fb = (bits >> 9) | 0x3f800000u;
    float u = __uint_as_float(fb) - 1.0f;
    u = fmaxf(u, 1.17549435e-38f);
    return -logf(-logf(u));
}

// ---------------------------------------------------------------------------
// Main fused kernel: 2048 blocks x 256 threads, TWO batches per block
// (M/pros amortized over both), 3-4 CTAs co-resident per SM for overlap.
// ---------------------------------------------------------------------------
#define XS_F    (G_PER_BLK * S_DIM * PITCH)      // 8704
#define PROS_F  (P_DIM * PITCH)                  // 4352
#define VS_F    (8 * PITCH)                      // 544
#define SBUF_F  (8 * PITCH)                      // 544: psum partials / xsel / loss
#define SMEM_FLOATS (XS_F + PROS_F + VS_F + 128 + SBUF_F + 64 + 64 + 8 + 8)
#define SMEM_BYTES  (SMEM_FLOATS * 4)

__global__ void __launch_bounds__(THREADS, 3) main_kernel(
    const float* __restrict__ x,
    const float* __restrict__ prototypes,
    float* __restrict__ out)
{
    extern __shared__ float sm[];
    float* xs    = sm;                       // [g][s][PITCH]
    float* pros  = xs + XS_F;                // [p][PITCH]
    float* vs    = pros + PROS_F;            // [(g*4+n)][PITCH]
    float* psumb = vs + VS_F;                // [g][64]
    float* sbuf  = psumb + 128;              // psum partials [512] -> xsel [8][PITCH] -> loss [8]
    float* candv = sbuf + SBUF_F;            // [64]: [g][w][4]
    int*   candi = (int*)(candv + 64);       // [64]
    int*   isel  = candi + 64;               // [8]
    int*   psel  = isel + 8;                 // [8]
    __shared__ unsigned int amLast;

    float* xsel = sbuf;                      // alias (after psum phase done)

    const int tid  = threadIdx.x;
    const int lane = tid & 31;
    const int w    = tid >> 5;               // 0..7
    const int b0   = blockIdx.x * G_PER_BLK;

    // coords for (n, h)-style phases
    const int cn = tid >> 6;          // 0..3
    const int ch = tid & 63;          // 0..63
    // coords for score/d2 phases (n minor -> 4-way row multicast)
    const int sp = tid >> 2;          // s (score) or p (VQ), 0..63
    const int sn = tid & 3;

    // --- stage prototypes: 1024 float4 over 256 threads ---
    {
        const float4* pp4 = reinterpret_cast<const float4*>(prototypes);
#pragma unroll
        for (int j = 0; j < 4; ++j) {
            int i4 = j * 256 + tid;
            int p  = i4 >> 4;
            int k4 = i4 & 15;
            *reinterpret_cast<float4*>(&pros[p * PITCH + k4 * 4]) = pp4[i4];
        }
    }
    // --- stage pos = x + pe: 2048 float4 ---
    {
        const float4* xb4 = reinterpret_cast<const float4*>(x + (size_t)b0 * S_DIM * H_DIM);
        const float4* pe4 = reinterpret_cast<const float4*>(g_pe);
#pragma unroll
        for (int j = 0; j < 8; ++j) {
            int i4 = j * 256 + tid;
            int g  = i4 >> 10;
            int s  = (i4 >> 4) & 63;
            int h4 = i4 & 15;
            float4 xv = xb4[i4];
            float4 pv = pe4[i4 & 1023];
            float4 o;
            o.x = xv.x + pv.x; o.y = xv.y + pv.y;
            o.z = xv.z + pv.z; o.w = xv.w + pv.w;
            *reinterpret_cast<float4*>(&xs[(g * 64 + s) * PITCH + h4 * 4]) = o;
        }
    }

    // two gumbels per thread (independent chains -> ILP in LDG shadow)
    float gn0 = gumbel_at((uint32_t)(b0 + 0) * 256u + (uint32_t)sn * 64u + (uint32_t)sp);
    float gn1 = gumbel_at((uint32_t)(b0 + 1) * 256u + (uint32_t)sn * 64u + (uint32_t)sp);

    __syncthreads();

    // --- psum partials: thread (q, h) sums 16 s-values, both g ---
    {
        int q = tid >> 6;
#pragma unroll
        for (int g = 0; g < 2; ++g) {
            const float* base = &xs[(g * 64 + q * 16) * PITCH + ch];
            float ps = 0.f;
#pragma unroll
            for (int s16 = 0; s16 < 16; ++s16)
                ps += base[s16 * PITCH];
            sbuf[g * 256 + tid] = ps;     // [g][q*64+h]
        }
    }
    __syncthreads();
    if (tid < 128) {
        int g = tid >> 6, h = tid & 63;
        psumb[tid] = sbuf[g * 256 + h] + sbuf[g * 256 + 64 + h]
                   + sbuf[g * 256 + 128 + h] + sbuf[g * 256 + 192 + h];
    }
    __syncthreads();

    // --- v[g][n][h]: M loaded ONCE, both batches accumulated ---
    {
        const float* Mt = g_M + ((size_t)cn * 64) * 64 + ch;   // stride 64 per k
        float a0 = 0.f, a1 = 0.f;
#pragma unroll
        for (int j = 0; j < 16; ++j) {
            float m0 = Mt[(j * 4 + 0) * 64];
            float m1 = Mt[(j * 4 + 1) * 64];
            float m2 = Mt[(j * 4 + 2) * 64];
            float m3 = Mt[(j * 4 + 3) * 64];
            float4 p0 = *reinterpret_cast<const float4*>(&psumb[ 0 + j * 4]);
            float4 p1 = *reinterpret_cast<const float4*>(&psumb[64 + j * 4]);
            a0 += m0 * p0.x + m1 * p0.y + m2 * p0.z + m3 * p0.w;
            a1 += m0 * p1.x + m1 * p1.y + m2 * p1.z + m3 * p1.w;
        }
        vs[(0 * 4 + cn) * PITCH + ch] = a0 * (1.0f / 512.0f);
        vs[(1 * 4 + cn) * PITCH + ch] = a1 * (1.0f / 512.0f);
    }
    __syncthreads();

    // --- score[g][n][s] = pos[g][s] . v[g][n] + gumbel; per-g warp argmax ---
#pragma unroll
    for (int g = 0; g < 2; ++g) {
        const float4* pr4 = reinterpret_cast<const float4*>(&xs[(g * 64 + sp) * PITCH]);
        const float4* vr4 = reinterpret_cast<const float4*>(&vs[(g * 4 + sn) * PITCH]);
        float lg = 0.f;
#pragma unroll
        for (int h4 = 0; h4 < 16; ++h4) {
            float4 a = pr4[h4], v = vr4[h4];
            lg += a.x * v.x + a.y * v.y + a.z * v.z + a.w * v.w;
        }
        float v = lg + (g ? gn1 : gn0);
        int idx = sp;
#pragma unroll
        for (int off = 4; off <= 16; off <<= 1) {
            float ov = __shfl_xor_sync(0xFFFFFFFFu, v, off);
            int   oi = __shfl_xor_sync(0xFFFFFFFFu, idx, off);
            if (ov > v || (ov == v && oi < idx)) { v = ov; idx = oi; }
        }
        if (lane < 4) { candv[g * 32 + w * 4 + lane] = v; candi[g * 32 + w * 4 + lane] = idx; }
    }
    __syncthreads();
    if (tid < 8) {      // combine 8 warps per (g,n), first-max (warps ascend in s)
        int g = tid >> 2, n = tid & 3;
        float best = candv[g * 32 + n];
        int   bi   = candi[g * 32 + n];
        for (int wb = 1; wb < 8; ++wb) {
            float v = candv[g * 32 + wb * 4 + n];
            int   i = candi[g * 32 + wb * 4 + n];
            if (v > best || (v == best && i < bi)) { best = v; bi = i; }
        }
        isel[tid] = bi;
        out[OFF_IDX + (size_t)(b0 + g) * N_SEL + n] = (float)bi;
    }
    __syncthreads();

    // --- gather selected raw x rows (sbuf now reused as xsel) ---
#pragma unroll
    for (int g = 0; g < 2; ++g)
        xsel[(g * 4 + cn) * PITCH + ch] =
            x[((size_t)(b0 + g) * S_DIM + isel[g * 4 + cn]) * H_DIM + ch];
    __syncthreads();

    // --- VQ relative distance d[g][n][p] = pros[p].(pros[p] - 2*xsel[g][n]) ---
#pragma unroll
    for (int g = 0; g < 2; ++g) {
        const float4* prow4 = reinterpret_cast<const float4*>(&pros[sp * PITCH]);
        const float4* xr4   = reinterpret_cast<const float4*>(&xsel[(g * 4 + sn) * PITCH]);
        float d = 0.f;
#pragma unroll
        for (int k4 = 0; k4 < 16; ++k4) {
            float4 pv = prow4[k4], xv = xr4[k4];
            d += pv.x * (pv.x - 2.0f * xv.x);
            d += pv.y * (pv.y - 2.0f * xv.y);
            d += pv.z * (pv.z - 2.0f * xv.z);
            d += pv.w * (pv.w - 2.0f * xv.w);
        }
        float v = d; int idx = sp;
#pragma unroll
        for (int off = 4; off <= 16; off <<= 1) {
            float ov = __shfl_xor_sync(0xFFFFFFFFu, v, off);
            int   oi = __shfl_xor_sync(0xFFFFFFFFu, idx, off);
            if (ov < v || (ov == v && oi < idx)) { v = ov; idx = oi; }
        }
        if (lane < 4) { candv[g * 32 + w * 4 + lane] = v; candi[g * 32 + w * 4 + lane] = idx; }
    }
    __syncthreads();
    if (tid < 8) {      // combine, first-min
        int g = tid >> 2, n = tid & 3;
        float best = candv[g * 32 + n];
        int   bi   = candi[g * 32 + n];
        for (int wb = 1; wb < 8; ++wb) {
            float v = candv[g * 32 + wb * 4 + n];
            int   i = candi[g * 32 + wb * 4 + n];
            if (v < best || (v == best && i < bi)) { best = v; bi = i; }
        }
        psel[tid] = bi;
    }
    __syncthreads();

    // --- outputs (reference rounding preserved) + loss contribution ---
    float losspart = 0.f;
#pragma unroll
    for (int g = 0; g < 2; ++g) {
        float xv  = xsel[(g * 4 + cn) * PITCH + ch];
        float pv  = pros[psel[g * 4 + cn] * PITCH + ch];
        float d   = pv - xv;
        float pst = xv + d;
        size_t ob = (size_t)(b0 + g) * 256 + (size_t)tid;
        out[ob]           = pst;
        out[OFF_RES + ob] = xv - pst;
        losspart += d * d;
    }
    __syncthreads();   // all xsel reads done before sbuf is reused for loss

    // --- deterministic loss reduction (warp shuffle + smem combine) ---
    {
        float v = losspart;
#pragma unroll
        for (int off = 16; off > 0; off >>= 1)
            v += __shfl_xor_sync(0xFFFFFFFFu, v, off);
        if (lane == 0) sbuf[w] = v;
    }
    __syncthreads();
    if (tid < 32) {
        float v = (tid < 8) ? sbuf[tid] : 0.f;
#pragma unroll
        for (int off = 16; off > 0; off >>= 1)
            v += __shfl_xor_sync(0xFFFFFFFFu, v, off);
        if (tid == 0) g_partial[blockIdx.x] = v;
    }

    // --- fused loss finalize: last block sums 2048 partials in fixed order ---
    __threadfence();
    if (tid == 0)
        amLast = (atomicAdd(&g_count, 1u) == (unsigned)(NBLKS - 1)) ? 1u : 0u;
    __syncthreads();
    if (amLast) {
        __threadfence();
        float v = 0.f;
#pragma unroll
        for (int j = 0; j < 8; ++j)             // fixed order -> deterministic
            v += g_partial[j * 256 + tid];
#pragma unroll
        for (int off = 16; off > 0; off >>= 1)
            v += __shfl_xor_sync(0xFFFFFFFFu, v, off);
        if (lane == 0) sbuf[w] = v;
        __syncthreads();
        if (tid < 32) {
            float s = (tid < 8) ? sbuf[tid] : 0.f;
#pragma unroll
            for (int off = 16; off > 0; off >>= 1)
                s += __shfl_xor_sync(0xFFFFFFFFu, s, off);
            if (tid == 0) {
                out[OFF_LOSS] = s * 1.25f / (float)(B_TOT * N_SEL * H_DIM);
                g_count = 0;            // reset for next graph replay
            }
        }
    }
}

// ---------------------------------------------------------------------------
extern "C" void kernel_launch(void* const* d_in, const int* in_sizes, int n_in,
                              void* d_out, int out_size) {
    (void)in_sizes; (void)n_in; (void)out_size;
    const float* x  = (const float*)d_in[0];
    const float* Wq = (const float*)d_in[1];
    const float* Wk = (const float*)d_in[2];
    const float* pr = (const float*)d_in[3];
    float* out = (float*)d_out;

    cudaFuncSetAttribute(main_kernel,
                         cudaFuncAttributeMaxDynamicSharedMemorySize, SMEM_BYTES);

    prep_kernel<<<260, 64>>>(Wq, Wk);
    main_kernel<<<NBLKS, THREADS, SMEM_BYTES>>>(x, pr, out);
}

// round 13
// speedup vs baseline: 1.7138x; 1.0192x over previous
#include <cuda_runtime.h>
#include <cstdint>

// Problem constants
#define B_TOT   4096
#define S_DIM   64
#define H_DIM   64
#define N_SEL   4
#define ATT_DIM 128
#define P_DIM   64

#define G_PER_BLK 2
#define NBLKS (B_TOT / G_PER_BLK)        // 2048
#define THREADS 256
#define PITCH 68                          // smem row pitch (floats), 16B-aligned

// Output layout (flatten-concat, float32):
#define OFF_RES  1048576u
#define OFF_LOSS 2097152u
#define OFF_IDX  2097153u

// Scratch (no allocations allowed -> device globals)
// M_t layout: g_M[(n*64 + k)*64 + h]  (k-major rows, h contiguous -> coalesced)
__device__ __align__(16) float g_M[N_SEL * H_DIM * H_DIM];
__device__ __align__(16) float g_pe[S_DIM * H_DIM];
__device__ float g_partial[NBLKS];
__device__ unsigned int g_count;          // zero-init; last block resets -> replay-safe

// ---------------------------------------------------------------------------
// Fused prep: blocks [0,256): M_t[n][k][h] = sum_a Wq[n,a,h]*Wk[n,a,k]
//             blocks [256,260): positional encoding (numpy-f32 rounding)
// ---------------------------------------------------------------------------
__global__ void prep_kernel(const float* __restrict__ Wq, const float* __restrict__ Wk) {
    const float c = (float)(-0.14391156056944368);   // f32(-ln(1e4)/64)
    if (blockIdx.x < 256) {
        int nk = blockIdx.x;
        int h  = threadIdx.x;
        int n  = nk >> 6;
        int k  = nk & 63;
        const float* wq = Wq + (size_t)n * ATT_DIM * H_DIM + h;   // lane-coalesced
        const float* wk = Wk + (size_t)n * ATT_DIM * H_DIM + k;   // broadcast
        float acc = 0.f;
#pragma unroll 8
        for (int a = 0; a < ATT_DIM; ++a)
            acc += wq[a * H_DIM] * wk[a * H_DIM];
        g_M[nk * 64 + h] = acc;           // [(n*64+k)*64 + h]
    } else {
        int base = (blockIdx.x - 256) * 1024;
#pragma unroll
        for (int k = 0; k < 16; ++k) {
            int idx = base + k * 64 + threadIdx.x;
            int s = idx >> 6, h = idx & 63;
            float arg  = (float)(h & ~1) * c;
            float divf = (float)exp((double)arg);
            float ang  = (float)s * divf;
            double sv  = (h & 1) ? cos((double)ang) : sin((double)ang);
            g_pe[idx] = (float)sv;
        }
    }
}

// ---------------------------------------------------------------------------
// threefry2x32, JAX partitionable mode: counter -> (0, gi), key (0,1),
// 32-bit draw = out0 ^ out1; uniform -> gumbel (bit-fidelity is load-bearing)
// ---------------------------------------------------------------------------
__device__ __forceinline__ uint32_t rotl32(uint32_t x, int d) {
    return (x << d) | (x >> (32 - d));
}

__device__ __forceinline__ float gumbel_at(uint32_t gi) {
    const uint32_t k0 = 0u, k1 = 1u, k2 = 0x1BD11BDBu;
    uint32_t x0 = 0u + k0;
    uint32_t x1 = gi + k1;
#define TF_ROUND(r) { x0 += x1; x1 = rotl32(x1, (r)); x1 ^= x0; }
    TF_ROUND(13) TF_ROUND(15) TF_ROUND(26) TF_ROUND(6)
    x0 += k1; x1 += k2 + 1u;
    TF_ROUND(17) TF_ROUND(29) TF_ROUND(16) TF_ROUND(24)
    x0 += k2; x1 += k0 + 2u;
    TF_ROUND(13) TF_ROUND(15) TF_ROUND(26) TF_ROUND(6)
    x0 += k0; x1 += k1 + 3u;
    TF_ROUND(17) TF_ROUND(29) TF_ROUND(16) TF_ROUND(24)
    x0 += k1; x1 += k2 + 4u;
    TF_ROUND(13) TF_ROUND(15) TF_ROUND(26) TF_ROUND(6)
    x0 += k2; x1 += k0 + 5u;
#undef TF_ROUND
    uint32_t bits = x0 ^ x1;
    uint32_t fb = (bits >> 9) | 0x3f800000u;
    float u = __uint_as_float(fb) - 1.0f;
    u = fmaxf(u, 1.17549435e-38f);
    return -logf(-logf(u));
}

// ---------------------------------------------------------------------------
// Main fused kernel: 2048 blocks x 256 threads, TWO batches per block.
// psum folded into staging (register accumulation + shfl pair-reduce);
// VQ reads each pros row once for both batches.
// ---------------------------------------------------------------------------
#define XS_F    (G_PER_BLK * S_DIM * PITCH)      // 8704
#define PROS_F  (P_DIM * PITCH)                  // 4352
#define VS_F    (8 * PITCH)                      // 544
#define SBUF_F  1024                              // psum float4 partials / xsel / loss
#define SMEM_FLOATS (XS_F + PROS_F + VS_F + 128 + SBUF_F + 64 + 64 + 8 + 8)
#define SMEM_BYTES  (SMEM_FLOATS * 4)

__global__ void __launch_bounds__(THREADS, 3) main_kernel(
    const float* __restrict__ x,
    const float* __restrict__ prototypes,
    float* __restrict__ out)
{
    extern __shared__ float sm[];
    float* xs    = sm;                       // [g][s][PITCH]
    float* pros  = xs + XS_F;                // [p][PITCH]
    float* vs    = pros + PROS_F;            // [(g*4+n)][PITCH]
    float* psumb = vs + VS_F;                // [g][64]
    float* sbuf  = psumb + 128;              // part4 [2][8][16]f4 -> xsel [8][PITCH] -> loss [8]
    float* candv = sbuf + SBUF_F;            // [64]: [g][w][4]
    int*   candi = (int*)(candv + 64);       // [64]
    int*   isel  = candi + 64;               // [8]
    int*   psel  = isel + 8;                 // [8]
    __shared__ unsigned int amLast;

    float* xsel = sbuf;                      // alias (after psum combine done)

    const int tid  = threadIdx.x;
    const int lane = tid & 31;
    const int w    = tid >> 5;               // 0..7
    const int b0   = blockIdx.x * G_PER_BLK;

    // coords for (n, h)-style phases
    const int cn = tid >> 6;          // 0..3
    const int ch = tid & 63;          // 0..63
    // coords for score/d2 phases (n minor -> 4-way row multicast)
    const int sp = tid >> 2;          // s (score) or p (VQ), 0..63
    const int sn = tid & 3;

    // --- stage prototypes: 1024 float4 over 256 threads ---
    {
        const float4* pp4 = reinterpret_cast<const float4*>(prototypes);
#pragma unroll
        for (int j = 0; j < 4; ++j) {
            int i4 = j * 256 + tid;
            int p  = i4 >> 4;
            int k4 = i4 & 15;
            *reinterpret_cast<float4*>(&pros[p * PITCH + k4 * 4]) = pp4[i4];
        }
    }
    // --- stage pos = x + pe AND accumulate psum partials in registers:
    //     for fixed tid, all 8 staged float4s share h4 = tid&15 while s sweeps ---
    float4 acc0 = make_float4(0.f, 0.f, 0.f, 0.f);
    float4 acc1 = make_float4(0.f, 0.f, 0.f, 0.f);
    {
        const float4* xb4 = reinterpret_cast<const float4*>(x + (size_t)b0 * S_DIM * H_DIM);
        const float4* pe4 = reinterpret_cast<const float4*>(g_pe);
#pragma unroll
        for (int j = 0; j < 8; ++j) {
            int i4 = j * 256 + tid;
            int g  = i4 >> 10;
            int s  = (i4 >> 4) & 63;
            int h4 = i4 & 15;
            float4 xv = xb4[i4];
            float4 pv = pe4[i4 & 1023];
            float4 o;
            o.x = xv.x + pv.x; o.y = xv.y + pv.y;
            o.z = xv.z + pv.z; o.w = xv.w + pv.w;
            *reinterpret_cast<float4*>(&xs[(g * 64 + s) * PITCH + h4 * 4]) = o;
            if (g == 0) { acc0.x += o.x; acc0.y += o.y; acc0.z += o.z; acc0.w += o.w; }
            else        { acc1.x += o.x; acc1.y += o.y; acc1.z += o.z; acc1.w += o.w; }
        }
    }
    // pair-reduce: tid and tid^16 share (g span, h4); both get the pair sum
    acc0.x += __shfl_xor_sync(0xFFFFFFFFu, acc0.x, 16);
    acc0.y += __shfl_xor_sync(0xFFFFFFFFu, acc0.y, 16);
    acc0.z += __shfl_xor_sync(0xFFFFFFFFu, acc0.z, 16);
    acc0.w += __shfl_xor_sync(0xFFFFFFFFu, acc0.w, 16);
    acc1.x += __shfl_xor_sync(0xFFFFFFFFu, acc1.x, 16);
    acc1.y += __shfl_xor_sync(0xFFFFFFFFu, acc1.y, 16);
    acc1.z += __shfl_xor_sync(0xFFFFFFFFu, acc1.z, 16);
    acc1.w += __shfl_xor_sync(0xFFFFFFFFu, acc1.w, 16);
    if (lane < 16) {
        float4* p4 = reinterpret_cast<float4*>(sbuf);
        p4[(0 * 8 + w) * 16 + lane] = acc0;   // [g][w][h4]
        p4[(1 * 8 + w) * 16 + lane] = acc1;
    }

    // two gumbels per thread (independent chains -> ILP in LDG shadow)
    float gn0 = gumbel_at((uint32_t)(b0 + 0) * 256u + (uint32_t)sn * 64u + (uint32_t)sp);
    float gn1 = gumbel_at((uint32_t)(b0 + 1) * 256u + (uint32_t)sn * 64u + (uint32_t)sp);

    __syncthreads();

    // --- psum combine: psumb[g*64+h] = sum_w sbuf[g*512 + w*64 + h] ---
    if (tid < 128) {
        int g = tid >> 6, h = tid & 63;
        const float* pb = sbuf + g * 512 + h;
        float s = 0.f;
#pragma unroll
        for (int wb = 0; wb < 8; ++wb)
            s += pb[wb * 64];
        psumb[tid] = s;
    }
    __syncthreads();

    // --- v[g][n][h]: M loaded ONCE, both batches accumulated ---
    {
        const float* Mt = g_M + ((size_t)cn * 64) * 64 + ch;   // stride 64 per k
        float a0 = 0.f, a1 = 0.f;
#pragma unroll
        for (int j = 0; j < 16; ++j) {
            float m0 = Mt[(j * 4 + 0) * 64];
            float m1 = Mt[(j * 4 + 1) * 64];
            float m2 = Mt[(j * 4 + 2) * 64];
            float m3 = Mt[(j * 4 + 3) * 64];
            float4 p0 = *reinterpret_cast<const float4*>(&psumb[ 0 + j * 4]);
            float4 p1 = *reinterpret_cast<const float4*>(&psumb[64 + j * 4]);
            a0 += m0 * p0.x + m1 * p0.y + m2 * p0.z + m3 * p0.w;
            a1 += m0 * p1.x + m1 * p1.y + m2 * p1.z + m3 * p1.w;
        }
        vs[(0 * 4 + cn) * PITCH + ch] = a0 * (1.0f / 512.0f);
        vs[(1 * 4 + cn) * PITCH + ch] = a1 * (1.0f / 512.0f);
    }
    __syncthreads();

    // --- score[g][n][s] = pos[g][s] . v[g][n] + gumbel; per-g warp argmax ---
#pragma unroll
    for (int g = 0; g < 2; ++g) {
        const float4* pr4 = reinterpret_cast<const float4*>(&xs[(g * 64 + sp) * PITCH]);
        const float4* vr4 = reinterpret_cast<const float4*>(&vs[(g * 4 + sn) * PITCH]);
        float lg = 0.f;
#pragma unroll
        for (int h4 = 0; h4 < 16; ++h4) {
            float4 a = pr4[h4], v = vr4[h4];
            lg += a.x * v.x + a.y * v.y + a.z * v.z + a.w * v.w;
        }
        float v = lg + (g ? gn1 : gn0);
        int idx = sp;
#pragma unroll
        for (int off = 4; off <= 16; off <<= 1) {
            float ov = __shfl_xor_sync(0xFFFFFFFFu, v, off);
            int   oi = __shfl_xor_sync(0xFFFFFFFFu, idx, off);
            if (ov > v || (ov == v && oi < idx)) { v = ov; idx = oi; }
        }
        if (lane < 4) { candv[g * 32 + w * 4 + lane] = v; candi[g * 32 + w * 4 + lane] = idx; }
    }
    __syncthreads();
    if (tid < 8) {      // combine 8 warps per (g,n), first-max (warps ascend in s)
        int g = tid >> 2, n = tid & 3;
        float best = candv[g * 32 + n];
        int   bi   = candi[g * 32 + n];
        for (int wb = 1; wb < 8; ++wb) {
            float v = candv[g * 32 + wb * 4 + n];
            int   i = candi[g * 32 + wb * 4 + n];
            if (v > best || (v == best && i < bi)) { best = v; bi = i; }
        }
        isel[tid] = bi;
        out[OFF_IDX + (size_t)(b0 + g) * N_SEL + n] = (float)bi;
    }
    __syncthreads();

    // --- gather selected raw x rows (sbuf now reused as xsel) ---
#pragma unroll
    for (int g = 0; g < 2; ++g)
        xsel[(g * 4 + cn) * PITCH + ch] =
            x[((size_t)(b0 + g) * S_DIM + isel[g * 4 + cn]) * H_DIM + ch];
    __syncthreads();

    // --- VQ: pros row loaded ONCE, distances for both batches ---
    {
        const float4* prow4 = reinterpret_cast<const float4*>(&pros[sp * PITCH]);
        const float4* x0 = reinterpret_cast<const float4*>(&xsel[(0 * 4 + sn) * PITCH]);
        const float4* x1 = reinterpret_cast<const float4*>(&xsel[(1 * 4 + sn) * PITCH]);
        float d0 = 0.f, d1 = 0.f;
#pragma unroll
        for (int k4 = 0; k4 < 16; ++k4) {
            float4 pv = prow4[k4], a = x0[k4], b = x1[k4];
            d0 += pv.x * (pv.x - 2.0f * a.x);
            d0 += pv.y * (pv.y - 2.0f * a.y);
            d0 += pv.z * (pv.z - 2.0f * a.z);
            d0 += pv.w * (pv.w - 2.0f * a.w);
            d1 += pv.x * (pv.x - 2.0f * b.x);
            d1 += pv.y * (pv.y - 2.0f * b.y);
            d1 += pv.z * (pv.z - 2.0f * b.z);
            d1 += pv.w * (pv.w - 2.0f * b.w);
        }
#pragma unroll
        for (int g = 0; g < 2; ++g) {
            float v = g ? d1 : d0;
            int idx = sp;
#pragma unroll
            for (int off = 4; off <= 16; off <<= 1) {
                float ov = __shfl_xor_sync(0xFFFFFFFFu, v, off);
                int   oi = __shfl_xor_sync(0xFFFFFFFFu, idx, off);
                if (ov < v || (ov == v && oi < idx)) { v = ov; idx = oi; }
            }
            if (lane < 4) { candv[g * 32 + w * 4 + lane] = v; candi[g * 32 + w * 4 + lane] = idx; }
        }
    }
    __syncthreads();
    if (tid < 8) {      // combine, first-min
        int g = tid >> 2, n = tid & 3;
        float best = candv[g * 32 + n];
        int   bi   = candi[g * 32 + n];
        for (int wb = 1; wb < 8; ++wb) {
            float v = candv[g * 32 + wb * 4 + n];
            int   i = candi[g * 32 + wb * 4 + n];
            if (v < best || (v == best && i < bi)) { best = v; bi = i; }
        }
        psel[tid] = bi;
    }
    __syncthreads();

    // --- outputs (reference rounding preserved) + loss contribution ---
    float losspart = 0.f;
#pragma unroll
    for (int g = 0; g < 2; ++g) {
        float xv  = xsel[(g * 4 + cn) * PITCH + ch];
        float pv  = pros[psel[g * 4 + cn] * PITCH + ch];
        float d   = pv - xv;
        float pst = xv + d;
        size_t ob = (size_t)(b0 + g) * 256 + (size_t)tid;
        out[ob]           = pst;
        out[OFF_RES + ob] = xv - pst;
        losspart += d * d;
    }
    __syncthreads();   // all xsel reads done before sbuf is reused for loss

    // --- deterministic loss reduction (warp shuffle + smem combine) ---
    {
        float v = losspart;
#pragma unroll
        for (int off = 16; off > 0; off >>= 1)
            v += __shfl_xor_sync(0xFFFFFFFFu, v, off);
        if (lane == 0) sbuf[w] = v;
    }
    __syncthreads();
    if (tid < 32) {
        float v = (tid < 8) ? sbuf[tid] : 0.f;
#pragma unroll
        for (int off = 16; off > 0; off >>= 1)
            v += __shfl_xor_sync(0xFFFFFFFFu, v, off);
        if (tid == 0) g_partial[blockIdx.x] = v;
    }

    // --- fused loss finalize: last block sums 2048 partials in fixed order ---
    __threadfence();
    if (tid == 0)
        amLast = (atomicAdd(&g_count, 1u) == (unsigned)(NBLKS - 1)) ? 1u : 0u;
    __syncthreads();
    if (amLast) {
        __threadfence();
        float v = 0.f;
#pragma unroll
        for (int j = 0; j < 8; ++j)             // fixed order -> deterministic
            v += g_partial[j * 256 + tid];
#pragma unroll
        for (int off = 16; off > 0; off >>= 1)
            v += __shfl_xor_sync(0xFFFFFFFFu, v, off);
        if (lane == 0) sbuf[w] = v;
        __syncthreads();
        if (tid < 32) {
            float s = (tid < 8) ? sbuf[tid] : 0.f;
#pragma unroll
            for (int off = 16; off > 0; off >>= 1)
                s += __shfl_xor_sync(0xFFFFFFFFu, s, off);
            if (tid == 0) {
                out[OFF_LOSS] = s * 1.25f / (float)(B_TOT * N_SEL * H_DIM);
                g_count = 0;            // reset for next graph replay
            }
        }
    }
}

// ---------------------------------------------------------------------------
extern "C" void kernel_launch(void* const* d_in, const int* in_sizes, int n_in,
                              void* d_out, int out_size) {
    (void)in_sizes; (void)n_in; (void)out_size;
    const float* x  = (const float*)d_in[0];
    const float* Wq = (const float*)d_in[1];
    const float* Wk = (const float*)d_in[2];
    const float* pr = (const float*)d_in[3];
    float* out = (float*)d_out;

    cudaFuncSetAttribute(main_kernel,
                         cudaFuncAttributeMaxDynamicSharedMemorySize, SMEM_BYTES);

    prep_kernel<<<260, 64>>>(Wq, Wk);
    main_kernel<<<NBLKS, THREADS, SMEM_BYTES>>>(x, pr, out);
}

// round 14
// speedup vs baseline: 1.8292x; 1.0673x over previous
#include <cuda_runtime.h>
#include <cstdint>

// Problem constants
#define B_TOT   4096
#define S_DIM   64
#define H_DIM   64
#define N_SEL   4
#define ATT_DIM 128
#define P_DIM   64

#define G_PER_BLK 2
#define NBLKS (B_TOT / G_PER_BLK)        // 2048
#define THREADS 256
#define PITCH 68                          // smem row pitch (floats), 16B-aligned

// Output layout (flatten-concat, float32):
#define OFF_RES  1048576u
#define OFF_LOSS 2097152u
#define OFF_IDX  2097153u

// Scratch (no allocations allowed -> device globals)
// M_t layout: g_M[(n*64 + k)*64 + h]  (k-major rows, h contiguous -> coalesced)
__device__ __align__(16) float g_M[N_SEL * H_DIM * H_DIM];
__device__ __align__(16) float g_pe[S_DIM * H_DIM];
__device__ float g_partial[NBLKS];
__device__ unsigned int g_count;          // zero-init; last block resets -> replay-safe

// ---------------------------------------------------------------------------
// Fused prep (68 blocks x 256 threads):
//   blocks [0,64):  M_t[n][k][h] = sum_a Wq[n,a,h]*Wk[n,a,k]  (4 nk rows/block)
//   blocks [64,68): positional encoding (numpy-f32 rounding)
// ---------------------------------------------------------------------------
__global__ void prep_kernel(const float* __restrict__ Wq, const float* __restrict__ Wk) {
    const float c = (float)(-0.14391156056944368);   // f32(-ln(1e4)/64)
    if (blockIdx.x < 64) {
        int nk = blockIdx.x * 4 + (threadIdx.x >> 6);
        int h  = threadIdx.x & 63;
        int n  = nk >> 6;
        int k  = nk & 63;
        const float* wq = Wq + (size_t)n * ATT_DIM * H_DIM + h;   // lane-coalesced
        const float* wk = Wk + (size_t)n * ATT_DIM * H_DIM + k;   // broadcast
        float acc = 0.f;
#pragma unroll 8
        for (int a = 0; a < ATT_DIM; ++a)
            acc += wq[a * H_DIM] * wk[a * H_DIM];
        g_M[nk * 64 + h] = acc;           // [(n*64+k)*64 + h]
    } else {
        int base = (blockIdx.x - 64) * 1024;
#pragma unroll
        for (int k = 0; k < 4; ++k) {
            int idx = base + k * 256 + threadIdx.x;
            int s = idx >> 6, h = idx & 63;
            float arg  = (float)(h & ~1) * c;
            float divf = (float)exp((double)arg);
            float ang  = (float)s * divf;
            double sv  = (h & 1) ? cos((double)ang) : sin((double)ang);
            g_pe[idx] = (float)sv;
        }
    }
}

// ---------------------------------------------------------------------------
// threefry2x32, JAX partitionable mode: counter -> (0, gi), key (0,1),
// 32-bit draw = out0 ^ out1; uniform -> gumbel (bit-fidelity is load-bearing)
// ---------------------------------------------------------------------------
__device__ __forceinline__ uint32_t rotl32(uint32_t x, int d) {
    return (x << d) | (x >> (32 - d));
}

__device__ __forceinline__ float gumbel_at(uint32_t gi) {
    const uint32_t k0 = 0u, k1 = 1u, k2 = 0x1BD11BDBu;
    uint32_t x0 = 0u + k0;
    uint32_t x1 = gi + k1;
#define TF_ROUND(r) { x0 += x1; x1 = rotl32(x1, (r)); x1 ^= x0; }
    TF_ROUND(13) TF_ROUND(15) TF_ROUND(26) TF_ROUND(6)
    x0 += k1; x1 += k2 + 1u;
    TF_ROUND(17) TF_ROUND(29) TF_ROUND(16) TF_ROUND(24)
    x0 += k2; x1 += k0 + 2u;
    TF_ROUND(13) TF_ROUND(15) TF_ROUND(26) TF_ROUND(6)
    x0 += k0; x1 += k1 + 3u;
    TF_ROUND(17) TF_ROUND(29) TF_ROUND(16) TF_ROUND(24)
    x0 += k1; x1 += k2 + 4u;
    TF_ROUND(13) TF_ROUND(15) TF_ROUND(26) TF_ROUND(6)
    x0 += k2; x1 += k0 + 5u;
#undef TF_ROUND
    uint32_t bits = x0 ^ x1;
    uint32_t fb = (bits >> 9) | 0x3f800000u;
    float u = __uint_as_float(fb) - 1.0f;
    u = fmaxf(u, 1.17549435e-38f);
    return -logf(-logf(u));
}

// ---------------------------------------------------------------------------
// Main fused kernel: 2048 blocks x 256 threads, TWO batches per block.
// smem time-multiplexed: prototypes staged AFTER the score phase into the
// (then-dead) xs[g=0] region -> ~41 KB/CTA -> 4 CTAs/SM resident.
// ---------------------------------------------------------------------------
#define XS_F    (G_PER_BLK * S_DIM * PITCH)      // 8704 (pros aliases first 4352)
#define VS_F    (8 * PITCH)                      // 544
#define SBUF_F  1024                              // psum float4 partials / xsel / loss
#define SMEM_FLOATS (XS_F + VS_F + 128 + SBUF_F + 64 + 64 + 8 + 8)
#define SMEM_BYTES  (SMEM_FLOATS * 4)

__global__ void __launch_bounds__(THREADS, 4) main_kernel(
    const float* __restrict__ x,
    const float* __restrict__ prototypes,
    float* __restrict__ out)
{
    extern __shared__ float sm[];
    float* xs    = sm;                       // [g][s][PITCH]; pros aliases [0,4352)
    float* vs    = xs + XS_F;                // [(g*4+n)][PITCH]
    float* psumb = vs + VS_F;                // [g][64]
    float* sbuf  = psumb + 128;              // part4 [2][8][16]f4 -> xsel [8][PITCH] -> loss [8]
    float* candv = sbuf + SBUF_F;            // [64]: [g][w][4]
    int*   candi = (int*)(candv + 64);       // [64]
    int*   isel  = candi + 64;               // [8]
    int*   psel  = isel + 8;                 // [8]
    __shared__ unsigned int amLast;

    float* xsel = sbuf;                      // alias (after psum combine done)
    float* pros = sm;                        // alias over xs[g=0] (after score phase)

    const int tid  = threadIdx.x;
    const int lane = tid & 31;
    const int w    = tid >> 5;               // 0..7
    const int b0   = blockIdx.x * G_PER_BLK;

    // coords for (n, h)-style phases
    const int cn = tid >> 6;          // 0..3
    const int ch = tid & 63;          // 0..63
    // coords for score/d2 phases (n minor -> 4-way row multicast)
    const int sp = tid >> 2;          // s (score) or p (VQ), 0..63
    const int sn = tid & 3;

    // --- stage pos = x + pe AND accumulate psum partials in registers:
    //     for fixed tid, all 8 staged float4s share h4 = tid&15 while s sweeps ---
    float4 acc0 = make_float4(0.f, 0.f, 0.f, 0.f);
    float4 acc1 = make_float4(0.f, 0.f, 0.f, 0.f);
    {
        const float4* xb4 = reinterpret_cast<const float4*>(x + (size_t)b0 * S_DIM * H_DIM);
        const float4* pe4 = reinterpret_cast<const float4*>(g_pe);
#pragma unroll
        for (int j = 0; j < 8; ++j) {
            int i4 = j * 256 + tid;
            int g  = i4 >> 10;
            int s  = (i4 >> 4) & 63;
            int h4 = i4 & 15;
            float4 xv = xb4[i4];
            float4 pv = pe4[i4 & 1023];
            float4 o;
            o.x = xv.x + pv.x; o.y = xv.y + pv.y;
            o.z = xv.z + pv.z; o.w = xv.w + pv.w;
            *reinterpret_cast<float4*>(&xs[(g * 64 + s) * PITCH + h4 * 4]) = o;
            if (g == 0) { acc0.x += o.x; acc0.y += o.y; acc0.z += o.z; acc0.w += o.w; }
            else        { acc1.x += o.x; acc1.y += o.y; acc1.z += o.z; acc1.w += o.w; }
        }
    }
    // pair-reduce: tid and tid^16 share (g span, h4); both get the pair sum
    acc0.x += __shfl_xor_sync(0xFFFFFFFFu, acc0.x, 16);
    acc0.y += __shfl_xor_sync(0xFFFFFFFFu, acc0.y, 16);
    acc0.z += __shfl_xor_sync(0xFFFFFFFFu, acc0.z, 16);
    acc0.w += __shfl_xor_sync(0xFFFFFFFFu, acc0.w, 16);
    acc1.x += __shfl_xor_sync(0xFFFFFFFFu, acc1.x, 16);
    acc1.y += __shfl_xor_sync(0xFFFFFFFFu, acc1.y, 16);
    acc1.z += __shfl_xor_sync(0xFFFFFFFFu, acc1.z, 16);
    acc1.w += __shfl_xor_sync(0xFFFFFFFFu, acc1.w, 16);
    if (lane < 16) {
        float4* p4 = reinterpret_cast<float4*>(sbuf);
        p4[(0 * 8 + w) * 16 + lane] = acc0;   // [g][w][h4]
        p4[(1 * 8 + w) * 16 + lane] = acc1;
    }

    // two gumbels per thread (independent chains -> ILP in LDG shadow)
    float gn0 = gumbel_at((uint32_t)(b0 + 0) * 256u + (uint32_t)sn * 64u + (uint32_t)sp);
    float gn1 = gumbel_at((uint32_t)(b0 + 1) * 256u + (uint32_t)sn * 64u + (uint32_t)sp);

    __syncthreads();

    // --- psum combine: psumb[g*64+h] = sum_w sbuf[g*512 + w*64 + h] ---
    if (tid < 128) {
        int g = tid >> 6, h = tid & 63;
        const float* pb = sbuf + g * 512 + h;
        float s = 0.f;
#pragma unroll
        for (int wb = 0; wb < 8; ++wb)
            s += pb[wb * 64];
        psumb[tid] = s;
    }
    __syncthreads();

    // --- v[g][n][h]: M loaded ONCE, both batches accumulated ---
    {
        const float* Mt = g_M + ((size_t)cn * 64) * 64 + ch;   // stride 64 per k
        float a0 = 0.f, a1 = 0.f;
#pragma unroll
        for (int j = 0; j < 16; ++j) {
            float m0 = Mt[(j * 4 + 0) * 64];
            float m1 = Mt[(j * 4 + 1) * 64];
            float m2 = Mt[(j * 4 + 2) * 64];
            float m3 = Mt[(j * 4 + 3) * 64];
            float4 p0 = *reinterpret_cast<const float4*>(&psumb[ 0 + j * 4]);
            float4 p1 = *reinterpret_cast<const float4*>(&psumb[64 + j * 4]);
            a0 += m0 * p0.x + m1 * p0.y + m2 * p0.z + m3 * p0.w;
            a1 += m0 * p1.x + m1 * p1.y + m2 * p1.z + m3 * p1.w;
        }
        vs[(0 * 4 + cn) * PITCH + ch] = a0 * (1.0f / 512.0f);
        vs[(1 * 4 + cn) * PITCH + ch] = a1 * (1.0f / 512.0f);
    }
    __syncthreads();

    // --- score[g][n][s] = pos[g][s] . v[g][n] + gumbel; per-g warp argmax ---
#pragma unroll
    for (int g = 0; g < 2; ++g) {
        const float4* pr4 = reinterpret_cast<const float4*>(&xs[(g * 64 + sp) * PITCH]);
        const float4* vr4 = reinterpret_cast<const float4*>(&vs[(g * 4 + sn) * PITCH]);
        float lg = 0.f;
#pragma unroll
        for (int h4 = 0; h4 < 16; ++h4) {
            float4 a = pr4[h4], v = vr4[h4];
            lg += a.x * v.x + a.y * v.y + a.z * v.z + a.w * v.w;
        }
        float v = lg + (g ? gn1 : gn0);
        int idx = sp;
#pragma unroll
        for (int off = 4; off <= 16; off <<= 1) {
            float ov = __shfl_xor_sync(0xFFFFFFFFu, v, off);
            int   oi = __shfl_xor_sync(0xFFFFFFFFu, idx, off);
            if (ov > v || (ov == v && oi < idx)) { v = ov; idx = oi; }
        }
        if (lane < 4) { candv[g * 32 + w * 4 + lane] = v; candi[g * 32 + w * 4 + lane] = idx; }
    }
    __syncthreads();    // all xs reads complete -> xs[g=0] region reusable

    // --- stage prototypes into the dead xs region (overlaps argmax combine) ---
    {
        const float4* pp4 = reinterpret_cast<const float4*>(prototypes);
#pragma unroll
        for (int j = 0; j < 4; ++j) {
            int i4 = j * 256 + tid;
            int p  = i4 >> 4;
            int k4 = i4 & 15;
            *reinterpret_cast<float4*>(&pros[p * PITCH + k4 * 4]) = pp4[i4];
        }
    }
    if (tid < 8) {      // combine 8 warps per (g,n), first-max (warps ascend in s)
        int g = tid >> 2, n = tid & 3;
        float best = candv[g * 32 + n];
        int   bi   = candi[g * 32 + n];
        for (int wb = 1; wb < 8; ++wb) {
            float v = candv[g * 32 + wb * 4 + n];
            int   i = candi[g * 32 + wb * 4 + n];
            if (v > best || (v == best && i < bi)) { best = v; bi = i; }
        }
        isel[tid] = bi;
        out[OFF_IDX + (size_t)(b0 + g) * N_SEL + n] = (float)bi;
    }
    __syncthreads();

    // --- gather selected raw x rows (sbuf now reused as xsel) ---
#pragma unroll
    for (int g = 0; g < 2; ++g)
        xsel[(g * 4 + cn) * PITCH + ch] =
            x[((size_t)(b0 + g) * S_DIM + isel[g * 4 + cn]) * H_DIM + ch];
    __syncthreads();

    // --- VQ: pros row loaded ONCE, distances for both batches ---
    {
        const float4* prow4 = reinterpret_cast<const float4*>(&pros[sp * PITCH]);
        const float4* x0 = reinterpret_cast<const float4*>(&xsel[(0 * 4 + sn) * PITCH]);
        const float4* x1 = reinterpret_cast<const float4*>(&xsel[(1 * 4 + sn) * PITCH]);
        float d0 = 0.f, d1 = 0.f;
#pragma unroll
        for (int k4 = 0; k4 < 16; ++k4) {
            float4 pv = prow4[k4], a = x0[k4], b = x1[k4];
            d0 += pv.x * (pv.x - 2.0f * a.x);
            d0 += pv.y * (pv.y - 2.0f * a.y);
            d0 += pv.z * (pv.z - 2.0f * a.z);
            d0 += pv.w * (pv.w - 2.0f * a.w);
            d1 += pv.x * (pv.x - 2.0f * b.x);
            d1 += pv.y * (pv.y - 2.0f * b.y);
            d1 += pv.z * (pv.z - 2.0f * b.z);
            d1 += pv.w * (pv.w - 2.0f * b.w);
        }
#pragma unroll
        for (int g = 0; g < 2; ++g) {
            float v = g ? d1 : d0;
            int idx = sp;
#pragma unroll
            for (int off = 4; off <= 16; off <<= 1) {
                float ov = __shfl_xor_sync(0xFFFFFFFFu, v, off);
                int   oi = __shfl_xor_sync(0xFFFFFFFFu, idx, off);
                if (ov < v || (ov == v && oi < idx)) { v = ov; idx = oi; }
            }
            if (lane < 4) { candv[g * 32 + w * 4 + lane] = v; candi[g * 32 + w * 4 + lane] = idx; }
        }
    }
    __syncthreads();
    if (tid < 8) {      // combine, first-min
        int g = tid >> 2, n = tid & 3;
        float best = candv[g * 32 + n];
        int   bi   = candi[g * 32 + n];
        for (int wb = 1; wb < 8; ++wb) {
            float v = candv[g * 32 + wb * 4 + n];
            int   i = candi[g * 32 + wb * 4 + n];
            if (v < best || (v == best && i < bi)) { best = v; bi = i; }
        }
        psel[tid] = bi;
    }
    __syncthreads();

    // --- outputs (reference rounding preserved) + loss contribution ---
    float losspart = 0.f;
#pragma unroll
    for (int g = 0; g < 2; ++g) {
        float xv  = xsel[(g * 4 + cn) * PITCH + ch];
        float pv  = pros[psel[g * 4 + cn] * PITCH + ch];
        float d   = pv - xv;
        float pst = xv + d;
        size_t ob = (size_t)(b0 + g) * 256 + (size_t)tid;
        out[ob]           = pst;
        out[OFF_RES + ob] = xv - pst;
        losspart += d * d;
    }
    __syncthreads();   // all xsel reads done before sbuf is reused for loss

    // --- deterministic loss reduction (warp shuffle + smem combine) ---
    {
        float v = losspart;
#pragma unroll
        for (int off = 16; off > 0; off >>= 1)
            v += __shfl_xor_sync(0xFFFFFFFFu, v, off);
        if (lane == 0) sbuf[w] = v;
    }
    __syncthreads();
    if (tid < 32) {
        float v = (tid < 8) ? sbuf[tid] : 0.f;
#pragma unroll
        for (int off = 16; off > 0; off >>= 1)
            v += __shfl_xor_sync(0xFFFFFFFFu, v, off);
        if (tid == 0) g_partial[blockIdx.x] = v;
    }

    // --- fused loss finalize: last block sums 2048 partials in fixed order ---
    __threadfence();
    if (tid == 0)
        amLast = (atomicAdd(&g_count, 1u) == (unsigned)(NBLKS - 1)) ? 1u : 0u;
    __syncthreads();
    if (amLast) {
        __threadfence();
        float v = 0.f;
#pragma unroll
        for (int j = 0; j < 8; ++j)             // fixed order -> deterministic
            v += g_partial[j * 256 + tid];
#pragma unroll
        for (int off = 16; off > 0; off >>= 1)
            v += __shfl_xor_sync(0xFFFFFFFFu, v, off);
        if (lane == 0) sbuf[w] = v;
        __syncthreads();
        if (tid < 32) {
            float s = (tid < 8) ? sbuf[tid] : 0.f;
#pragma unroll
            for (int off = 16; off > 0; off >>= 1)
                s += __shfl_xor_sync(0xFFFFFFFFu, s, off);
            if (tid == 0) {
                out[OFF_LOSS] = s * 1.25f / (float)(B_TOT * N_SEL * H_DIM);
                g_count = 0;            // reset for next graph replay
            }
        }
    }
}

// ---------------------------------------------------------------------------
extern "C" void kernel_launch(void* const* d_in, const int* in_sizes, int n_in,
                              void* d_out, int out_size) {
    (void)in_sizes; (void)n_in; (void)out_size;
    const float* x  = (const float*)d_in[0];
    const float* Wq = (const float*)d_in[1];
    const float* Wk = (const float*)d_in[2];
    const float* pr = (const float*)d_in[3];
    float* out = (float*)d_out;

    cudaFuncSetAttribute(main_kernel,
                         cudaFuncAttributeMaxDynamicSharedMemorySize, SMEM_BYTES);

    prep_kernel<<<68, 256>>>(Wq, Wk);
    main_kernel<<<NBLKS, THREADS, SMEM_BYTES>>>(x, pr, out);
}

// round 15
// speedup vs baseline: 1.8945x; 1.0357x over previous
#include <cuda_runtime.h>
#include <cstdint>

// Problem constants
#define B_TOT   4096
#define S_DIM   64
#define H_DIM   64
#define N_SEL   4
#define ATT_DIM 128
#define P_DIM   64

#define G_PER_BLK 2
#define NBLKS (B_TOT / G_PER_BLK)        // 2048
#define THREADS 256
#define PITCH 68                          // smem row pitch (floats), 16B-aligned

// Output layout (flatten-concat, float32):
#define OFF_RES  1048576u
#define OFF_LOSS 2097152u
#define OFF_IDX  2097153u

// Scratch (no allocations allowed -> device globals)
// M_t layout: g_M[(n*64 + k)*64 + h]  (k-major rows, h contiguous -> coalesced)
__device__ __align__(16) float g_M[N_SEL * H_DIM * H_DIM];
__device__ __align__(16) float g_pe[S_DIM * H_DIM];
__device__ float g_partial[NBLKS];
__device__ unsigned int g_count;          // zero-init; last block resets -> replay-safe

// ---------------------------------------------------------------------------
// Fused prep (260 blocks x 256 threads):
//   blocks [0,256):  one nk row each; a-dim split 4 ways (threads (aq, h)) so
//                    the LDG chain is 32 long with ~14 warps/SM -> latency hidden
//   blocks [256,260): positional encoding (numpy-f32 rounding)
// ---------------------------------------------------------------------------
__global__ void prep_kernel(const float* __restrict__ Wq, const float* __restrict__ Wk) {
    const float c = (float)(-0.14391156056944368);   // f32(-ln(1e4)/64)
    if (blockIdx.x < 256) {
        __shared__ float part[4][64];
        int nk = blockIdx.x;
        int aq = threadIdx.x >> 6;        // a-quarter 0..3
        int h  = threadIdx.x & 63;
        int n  = nk >> 6;
        int k  = nk & 63;
        const float* wq = Wq + (size_t)n * ATT_DIM * H_DIM + (size_t)aq * 32 * H_DIM + h;
        const float* wk = Wk + (size_t)n * ATT_DIM * H_DIM + (size_t)aq * 32 * H_DIM + k;
        float acc = 0.f;
#pragma unroll 8
        for (int a = 0; a < 32; ++a)
            acc += wq[a * H_DIM] * wk[a * H_DIM];
        part[aq][h] = acc;
        __syncthreads();
        if (threadIdx.x < 64) {
            int hh = threadIdx.x;
            g_M[nk * 64 + hh] = ((part[0][hh] + part[1][hh]) + part[2][hh]) + part[3][hh];
        }
    } else {
        int base = (blockIdx.x - 256) * 1024;
#pragma unroll
        for (int kk = 0; kk < 4; ++kk) {
            int idx = base + kk * 256 + threadIdx.x;
            int s = idx >> 6, h = idx & 63;
            float arg  = (float)(h & ~1) * c;
            float divf = (float)exp((double)arg);
            float ang  = (float)s * divf;
            double sv  = (h & 1) ? cos((double)ang) : sin((double)ang);
            g_pe[idx] = (float)sv;
        }
    }
}

// ---------------------------------------------------------------------------
// threefry2x32, JAX partitionable mode: counter -> (0, gi), key (0,1),
// 32-bit draw = out0 ^ out1; uniform -> gumbel (bit-fidelity is load-bearing)
// ---------------------------------------------------------------------------
__device__ __forceinline__ uint32_t rotl32(uint32_t x, int d) {
    return (x << d) | (x >> (32 - d));
}

__device__ __forceinline__ float gumbel_at(uint32_t gi) {
    const uint32_t k0 = 0u, k1 = 1u, k2 = 0x1BD11BDBu;
    uint32_t x0 = 0u + k0;
    uint32_t x1 = gi + k1;
#define TF_ROUND(r) { x0 += x1; x1 = rotl32(x1, (r)); x1 ^= x0; }
    TF_ROUND(13) TF_ROUND(15) TF_ROUND(26) TF_ROUND(6)
    x0 += k1; x1 += k2 + 1u;
    TF_ROUND(17) TF_ROUND(29) TF_ROUND(16) TF_ROUND(24)
    x0 += k2; x1 += k0 + 2u;
    TF_ROUND(13) TF_ROUND(15) TF_ROUND(26) TF_ROUND(6)
    x0 += k0; x1 += k1 + 3u;
    TF_ROUND(17) TF_ROUND(29) TF_ROUND(16) TF_ROUND(24)
    x0 += k1; x1 += k2 + 4u;
    TF_ROUND(13) TF_ROUND(15) TF_ROUND(26) TF_ROUND(6)
    x0 += k2; x1 += k0 + 5u;
#undef TF_ROUND
    uint32_t bits = x0 ^ x1;
    uint32_t fb = (bits >> 9) | 0x3f800000u;
    float u = __uint_as_float(fb) - 1.0f;
    u = fmaxf(u, 1.17549435e-38f);
    return -logf(-logf(u));
}

// ---------------------------------------------------------------------------
// Main fused kernel: 2048 blocks x 256 threads, TWO batches per block,
// 4 CTAs/SM. pe loaded once per (s,h4) and reused for both batches.
// Prototypes staged into the dead xs[g=0] region after the score phase.
// ---------------------------------------------------------------------------
#define XS_F    (G_PER_BLK * S_DIM * PITCH)      // 8704 (pros aliases first 4352)
#define VS_F    (8 * PITCH)                      // 544
#define SBUF_F  1024                              // psum float4 partials / xsel / loss
#define SMEM_FLOATS (XS_F + VS_F + 128 + SBUF_F + 64 + 64 + 8 + 8)
#define SMEM_BYTES  (SMEM_FLOATS * 4)

__global__ void __launch_bounds__(THREADS, 4) main_kernel(
    const float* __restrict__ x,
    const float* __restrict__ prototypes,
    float* __restrict__ out)
{
    extern __shared__ float sm[];
    float* xs    = sm;                       // [g][s][PITCH]; pros aliases [0,4352)
    float* vs    = xs + XS_F;                // [(g*4+n)][PITCH]
    float* psumb = vs + VS_F;                // [g][64]
    float* sbuf  = psumb + 128;              // part4 [2][8][16]f4 -> xsel [8][PITCH] -> loss [8]
    float* candv = sbuf + SBUF_F;            // [64]: [g][w][4]
    int*   candi = (int*)(candv + 64);       // [64]
    int*   isel  = candi + 64;               // [8]
    int*   psel  = isel + 8;                 // [8]
    __shared__ unsigned int amLast;

    float* xsel = sbuf;                      // alias (after psum combine done)
    float* pros = sm;                        // alias over xs[g=0] (after score phase)

    const int tid  = threadIdx.x;
    const int lane = tid & 31;
    const int w    = tid >> 5;               // 0..7
    const int b0   = blockIdx.x * G_PER_BLK;

    // coords for (n, h)-style phases
    const int cn = tid >> 6;          // 0..3
    const int ch = tid & 63;          // 0..63
    // coords for score/d2 phases (n minor -> 4-way row multicast)
    const int sp = tid >> 2;          // s (score) or p (VQ), 0..63
    const int sn = tid & 3;

    // --- stage pos = x + pe AND accumulate psum partials in registers.
    //     pe dedup: iterations j and j+4 share the same pe float4 (i4&1023),
    //     so load pe once and apply to both batches. Accumulation order per
    //     acc register is unchanged (bit-identical psum partials). ---
    float4 acc0 = make_float4(0.f, 0.f, 0.f, 0.f);
    float4 acc1 = make_float4(0.f, 0.f, 0.f, 0.f);
    {
        const float4* xb4 = reinterpret_cast<const float4*>(x + (size_t)b0 * S_DIM * H_DIM);
        const float4* pe4 = reinterpret_cast<const float4*>(g_pe);
#pragma unroll
        for (int j = 0; j < 4; ++j) {
            int i4 = j * 256 + tid;           // g=0 index; g=1 index = i4 + 1024
            int s  = (i4 >> 4) & 63;
            int h4 = i4 & 15;
            float4 pv  = pe4[i4];             // shared by both batches
            float4 xv0 = xb4[i4];
            float4 xv1 = xb4[1024 + i4];
            float4 o0, o1;
            o0.x = xv0.x + pv.x; o0.y = xv0.y + pv.y;
            o0.z = xv0.z + pv.z; o0.w = xv0.w + pv.w;
            o1.x = xv1.x + pv.x; o1.y = xv1.y + pv.y;
            o1.z = xv1.z + pv.z; o1.w = xv1.w + pv.w;
            *reinterpret_cast<float4*>(&xs[(0 * 64 + s) * PITCH + h4 * 4]) = o0;
            *reinterpret_cast<float4*>(&xs[(1 * 64 + s) * PITCH + h4 * 4]) = o1;
            acc0.x += o0.x; acc0.y += o0.y; acc0.z += o0.z; acc0.w += o0.w;
            acc1.x += o1.x; acc1.y += o1.y; acc1.z += o1.z; acc1.w += o1.w;
        }
    }
    // pair-reduce: tid and tid^16 share (g span, h4); both get the pair sum
    acc0.x += __shfl_xor_sync(0xFFFFFFFFu, acc0.x, 16);
    acc0.y += __shfl_xor_sync(0xFFFFFFFFu, acc0.y, 16);
    acc0.z += __shfl_xor_sync(0xFFFFFFFFu, acc0.z, 16);
    acc0.w += __shfl_xor_sync(0xFFFFFFFFu, acc0.w, 16);
    acc1.x += __shfl_xor_sync(0xFFFFFFFFu, acc1.x, 16);
    acc1.y += __shfl_xor_sync(0xFFFFFFFFu, acc1.y, 16);
    acc1.z += __shfl_xor_sync(0xFFFFFFFFu, acc1.z, 16);
    acc1.w += __shfl_xor_sync(0xFFFFFFFFu, acc1.w, 16);
    if (lane < 16) {
        float4* p4 = reinterpret_cast<float4*>(sbuf);
        p4[(0 * 8 + w) * 16 + lane] = acc0;   // [g][w][h4]
        p4[(1 * 8 + w) * 16 + lane] = acc1;
    }

    // two gumbels per thread (independent chains -> ILP in LDG shadow)
    float gn0 = gumbel_at((uint32_t)(b0 + 0) * 256u + (uint32_t)sn * 64u + (uint32_t)sp);
    float gn1 = gumbel_at((uint32_t)(b0 + 1) * 256u + (uint32_t)sn * 64u + (uint32_t)sp);

    __syncthreads();

    // --- psum combine: psumb[g*64+h] = sum_w sbuf[g*512 + w*64 + h] ---
    if (tid < 128) {
        int g = tid >> 6, h = tid & 63;
        const float* pb = sbuf + g * 512 + h;
        float s = 0.f;
#pragma unroll
        for (int wb = 0; wb < 8; ++wb)
            s += pb[wb * 64];
        psumb[tid] = s;
    }
    __syncthreads();

    // --- v[g][n][h]: M loaded ONCE, both batches accumulated ---
    {
        const float* Mt = g_M + ((size_t)cn * 64) * 64 + ch;   // stride 64 per k
        float a0 = 0.f, a1 = 0.f;
#pragma unroll
        for (int j = 0; j < 16; ++j) {
            float m0 = Mt[(j * 4 + 0) * 64];
            float m1 = Mt[(j * 4 + 1) * 64];
            float m2 = Mt[(j * 4 + 2) * 64];
            float m3 = Mt[(j * 4 + 3) * 64];
            float4 p0 = *reinterpret_cast<const float4*>(&psumb[ 0 + j * 4]);
            float4 p1 = *reinterpret_cast<const float4*>(&psumb[64 + j * 4]);
            a0 += m0 * p0.x + m1 * p0.y + m2 * p0.z + m3 * p0.w;
            a1 += m0 * p1.x + m1 * p1.y + m2 * p1.z + m3 * p1.w;
        }
        vs[(0 * 4 + cn) * PITCH + ch] = a0 * (1.0f / 512.0f);
        vs[(1 * 4 + cn) * PITCH + ch] = a1 * (1.0f / 512.0f);
    }
    __syncthreads();

    // --- score[g][n][s] = pos[g][s] . v[g][n] + gumbel; per-g warp argmax ---
#pragma unroll
    for (int g = 0; g < 2; ++g) {
        const float4* pr4 = reinterpret_cast<const float4*>(&xs[(g * 64 + sp) * PITCH]);
        const float4* vr4 = reinterpret_cast<const float4*>(&vs[(g * 4 + sn) * PITCH]);
        float lg = 0.f;
#pragma unroll
        for (int h4 = 0; h4 < 16; ++h4) {
            float4 a = pr4[h4], v = vr4[h4];
            lg += a.x * v.x + a.y * v.y + a.z * v.z + a.w * v.w;
        }
        float v = lg + (g ? gn1 : gn0);
        int idx = sp;
#pragma unroll
        for (int off = 4; off <= 16; off <<= 1) {
            float ov = __shfl_xor_sync(0xFFFFFFFFu, v, off);
            int   oi = __shfl_xor_sync(0xFFFFFFFFu, idx, off);
            if (ov > v || (ov == v && oi < idx)) { v = ov; idx = oi; }
        }
        if (lane < 4) { candv[g * 32 + w * 4 + lane] = v; candi[g * 32 + w * 4 + lane] = idx; }
    }
    __syncthreads();    // all xs reads complete -> xs[g=0] region reusable

    // --- stage prototypes into the dead xs region (overlaps argmax combine) ---
    {
        const float4* pp4 = reinterpret_cast<const float4*>(prototypes);
#pragma unroll
        for (int j = 0; j < 4; ++j) {
            int i4 = j * 256 + tid;
            int p  = i4 >> 4;
            int k4 = i4 & 15;
            *reinterpret_cast<float4*>(&pros[p * PITCH + k4 * 4]) = pp4[i4];
        }
    }
    if (tid < 8) {      // combine 8 warps per (g,n), first-max (warps ascend in s)
        int g = tid >> 2, n = tid & 3;
        float best = candv[g * 32 + n];
        int   bi   = candi[g * 32 + n];
        for (int wb = 1; wb < 8; ++wb) {
            float v = candv[g * 32 + wb * 4 + n];
            int   i = candi[g * 32 + wb * 4 + n];
            if (v > best || (v == best && i < bi)) { best = v; bi = i; }
        }
        isel[tid] = bi;
        out[OFF_IDX + (size_t)(b0 + g) * N_SEL + n] = (float)bi;
    }
    __syncthreads();

    // --- gather selected raw x rows (sbuf now reused as xsel) ---
#pragma unroll
    for (int g = 0; g < 2; ++g)
        xsel[(g * 4 + cn) * PITCH + ch] =
            x[((size_t)(b0 + g) * S_DIM + isel[g * 4 + cn]) * H_DIM + ch];
    __syncthreads();

    // --- VQ: pros row loaded ONCE, distances for both batches ---
    {
        const float4* prow4 = reinterpret_cast<const float4*>(&pros[sp * PITCH]);
        const float4* x0 = reinterpret_cast<const float4*>(&xsel[(0 * 4 + sn) * PITCH]);
        const float4* x1 = reinterpret_cast<const float4*>(&xsel[(1 * 4 + sn) * PITCH]);
        float d0 = 0.f, d1 = 0.f;
#pragma unroll
        for (int k4 = 0; k4 < 16; ++k4) {
            float4 pv = prow4[k4], a = x0[k4], b = x1[k4];
            d0 += pv.x * (pv.x - 2.0f * a.x);
            d0 += pv.y * (pv.y - 2.0f * a.y);
            d0 += pv.z * (pv.z - 2.0f * a.z);
            d0 += pv.w * (pv.w - 2.0f * a.w);
            d1 += pv.x * (pv.x - 2.0f * b.x);
            d1 += pv.y * (pv.y - 2.0f * b.y);
            d1 += pv.z * (pv.z - 2.0f * b.z);
            d1 += pv.w * (pv.w - 2.0f * b.w);
        }
#pragma unroll
        for (int g = 0; g < 2; ++g) {
            float v = g ? d1 : d0;
            int idx = sp;
#pragma unroll
            for (int off = 4; off <= 16; off <<= 1) {
                float ov = __shfl_xor_sync(0xFFFFFFFFu, v, off);
                int   oi = __shfl_xor_sync(0xFFFFFFFFu, idx, off);
                if (ov < v || (ov == v && oi < idx)) { v = ov; idx = oi; }
            }
            if (lane < 4) { candv[g * 32 + w * 4 + lane] = v; candi[g * 32 + w * 4 + lane] = idx; }
        }
    }
    __syncthreads();
    if (tid < 8) {      // combine, first-min
        int g = tid >> 2, n = tid & 3;
        float best = candv[g * 32 + n];
        int   bi   = candi[g * 32 + n];
        for (int wb = 1; wb < 8; ++wb) {
            float v = candv[g * 32 + wb * 4 + n];
            int   i = candi[g * 32 + wb * 4 + n];
            if (v < best || (v == best && i < bi)) { best = v; bi = i; }
        }
        psel[tid] = bi;
    }
    __syncthreads();

    // --- outputs (reference rounding preserved) + loss contribution ---
    float losspart = 0.f;
#pragma unroll
    for (int g = 0; g < 2; ++g) {
        float xv  = xsel[(g * 4 + cn) * PITCH + ch];
        float pv  = pros[psel[g * 4 + cn] * PITCH + ch];
        float d   = pv - xv;
        float pst = xv + d;
        size_t ob = (size_t)(b0 + g) * 256 + (size_t)tid;
        out[ob]           = pst;
        out[OFF_RES + ob] = xv - pst;
        losspart += d * d;
    }
    __syncthreads();   // all xsel reads done before sbuf is reused for loss

    // --- deterministic loss reduction (warp shuffle + smem combine) ---
    {
        float v = losspart;
#pragma unroll
        for (int off = 16; off > 0; off >>= 1)
            v += __shfl_xor_sync(0xFFFFFFFFu, v, off);
        if (lane == 0) sbuf[w] = v;
    }
    __syncthreads();
    if (tid < 32) {
        float v = (tid < 8) ? sbuf[tid] : 0.f;
#pragma unroll
        for (int off = 16; off > 0; off >>= 1)
            v += __shfl_xor_sync(0xFFFFFFFFu, v, off);
        if (tid == 0) g_partial[blockIdx.x] = v;
    }

    // --- fused loss finalize: last block sums 2048 partials in fixed order ---
    __threadfence();
    if (tid == 0)
        amLast = (atomicAdd(&g_count, 1u) == (unsigned)(NBLKS - 1)) ? 1u : 0u;
    __syncthreads();
    if (amLast) {
        __threadfence();
        float v = 0.f;
#pragma unroll
        for (int j = 0; j < 8; ++j)             // fixed order -> deterministic
            v += g_partial[j * 256 + tid];
#pragma unroll
        for (int off = 16; off > 0; off >>= 1)
            v += __shfl_xor_sync(0xFFFFFFFFu, v, off);
        if (lane == 0) sbuf[w] = v;
        __syncthreads();
        if (tid < 32) {
            float s = (tid < 8) ? sbuf[tid] : 0.f;
#pragma unroll
            for (int off = 16; off > 0; off >>= 1)
                s += __shfl_xor_sync(0xFFFFFFFFu, s, off);
            if (tid == 0) {
                out[OFF_LOSS] = s * 1.25f / (float)(B_TOT * N_SEL * H_DIM);
                g_count = 0;            // reset for next graph replay
            }
        }
    }
}

// ---------------------------------------------------------------------------
extern "C" void kernel_launch(void* const* d_in, const int* in_sizes, int n_in,
                              void* d_out, int out_size) {
    (void)in_sizes; (void)n_in; (void)out_size;
    const float* x  = (const float*)d_in[0];
    const float* Wq = (const float*)d_in[1];
    const float* Wk = (const float*)d_in[2];
    const float* pr = (const float*)d_in[3];
    float* out = (float*)d_out;

    cudaFuncSetAttribute(main_kernel,
                         cudaFuncAttributeMaxDynamicSharedMemorySize, SMEM_BYTES);

    prep_kernel<<<260, 256>>>(Wq, Wk);
    main_kernel<<<NBLKS, THREADS, SMEM_BYTES>>>(x, pr, out);
}

// round 16
// speedup vs baseline: 1.8966x; 1.0011x over previous
#include <cuda_runtime.h>
#include <cstdint>

// Problem constants
#define B_TOT   4096
#define S_DIM   64
#define H_DIM   64
#define N_SEL   4
#define ATT_DIM 128
#define P_DIM   64

#define G_PER_BLK 2
#define NBLKS (B_TOT / G_PER_BLK)        // 2048
#define THREADS 256
#define PITCH 68                          // smem row pitch (floats), 16B-aligned

// Output layout (flatten-concat, float32):
#define OFF_RES  1048576u
#define OFF_LOSS 2097152u
#define OFF_IDX  2097153u

// Scratch (no allocations allowed -> device globals)
// M_t layout: g_M[(n*64 + k)*64 + h]  (k-major rows, h contiguous -> coalesced)
__device__ __align__(16) float g_M[N_SEL * H_DIM * H_DIM];
__device__ __align__(16) float g_pe[S_DIM * H_DIM];
__device__ float g_partial[NBLKS];
__device__ unsigned int g_count;          // zero-init; last block resets -> replay-safe

// ---------------------------------------------------------------------------
// Fused prep (260 blocks x 256 threads):
//   blocks [0,256):  one nk row each; a-dim split 4 ways (threads (aq, h)) so
//                    the LDG chain is 32 long with high occupancy -> latency hidden
//   blocks [256,260): positional encoding (numpy-f32 rounding)
// ---------------------------------------------------------------------------
__global__ void prep_kernel(const float* __restrict__ Wq, const float* __restrict__ Wk) {
    const float c = (float)(-0.14391156056944368);   // f32(-ln(1e4)/64)
    if (blockIdx.x < 256) {
        __shared__ float part[4][64];
        int nk = blockIdx.x;
        int aq = threadIdx.x >> 6;        // a-quarter 0..3
        int h  = threadIdx.x & 63;
        int n  = nk >> 6;
        int k  = nk & 63;
        const float* wq = Wq + (size_t)n * ATT_DIM * H_DIM + (size_t)aq * 32 * H_DIM + h;
        const float* wk = Wk + (size_t)n * ATT_DIM * H_DIM + (size_t)aq * 32 * H_DIM + k;
        float acc = 0.f;
#pragma unroll 8
        for (int a = 0; a < 32; ++a)
            acc += wq[a * H_DIM] * wk[a * H_DIM];
        part[aq][h] = acc;
        __syncthreads();
        if (threadIdx.x < 64) {
            int hh = threadIdx.x;
            g_M[nk * 64 + hh] = ((part[0][hh] + part[1][hh]) + part[2][hh]) + part[3][hh];
        }
    } else {
        int base = (blockIdx.x - 256) * 1024;
#pragma unroll
        for (int kk = 0; kk < 4; ++kk) {
            int idx = base + kk * 256 + threadIdx.x;
            int s = idx >> 6, h = idx & 63;
            float arg  = (float)(h & ~1) * c;
            float divf = (float)exp((double)arg);
            float ang  = (float)s * divf;
            double sv  = (h & 1) ? cos((double)ang) : sin((double)ang);
            g_pe[idx] = (float)sv;
        }
    }
}

// ---------------------------------------------------------------------------
// threefry2x32, JAX partitionable mode: counter -> (0, gi), key (0,1),
// 32-bit draw = out0 ^ out1; uniform -> gumbel (bit-fidelity is load-bearing)
// ---------------------------------------------------------------------------
__device__ __forceinline__ uint32_t rotl32(uint32_t x, int d) {
    return (x << d) | (x >> (32 - d));
}

__device__ __forceinline__ float gumbel_at(uint32_t gi) {
    const uint32_t k0 = 0u, k1 = 1u, k2 = 0x1BD11BDBu;
    uint32_t x0 = 0u + k0;
    uint32_t x1 = gi + k1;
#define TF_ROUND(r) { x0 += x1; x1 = rotl32(x1, (r)); x1 ^= x0; }
    TF_ROUND(13) TF_ROUND(15) TF_ROUND(26) TF_ROUND(6)
    x0 += k1; x1 += k2 + 1u;
    TF_ROUND(17) TF_ROUND(29) TF_ROUND(16) TF_ROUND(24)
    x0 += k2; x1 += k0 + 2u;
    TF_ROUND(13) TF_ROUND(15) TF_ROUND(26) TF_ROUND(6)
    x0 += k0; x1 += k1 + 3u;
    TF_ROUND(17) TF_ROUND(29) TF_ROUND(16) TF_ROUND(24)
    x0 += k1; x1 += k2 + 4u;
    TF_ROUND(13) TF_ROUND(15) TF_ROUND(26) TF_ROUND(6)
    x0 += k2; x1 += k0 + 5u;
#undef TF_ROUND
    uint32_t bits = x0 ^ x1;
    uint32_t fb = (bits >> 9) | 0x3f800000u;
    float u = __uint_as_float(fb) - 1.0f;
    u = fmaxf(u, 1.17549435e-38f);
    return -logf(-logf(u));
}

// ---------------------------------------------------------------------------
// Main fused kernel: 2048 blocks x 256 threads, TWO batches per block,
// 5 CTAs/SM (reg-capped at 51). Gumbels computed lazily in the score phase
// to shrink peak register live range; prototypes staged into the dead
// xs[g=0] region after the score phase.
// ---------------------------------------------------------------------------
#define XS_F    (G_PER_BLK * S_DIM * PITCH)      // 8704 (pros aliases first 4352)
#define VS_F    (8 * PITCH)                      // 544
#define SBUF_F  1024                              // psum float4 partials / xsel / loss
#define SMEM_FLOATS (XS_F + VS_F + 128 + SBUF_F + 64 + 64 + 8 + 8)
#define SMEM_BYTES  (SMEM_FLOATS * 4)

__global__ void __launch_bounds__(THREADS, 5) main_kernel(
    const float* __restrict__ x,
    const float* __restrict__ prototypes,
    float* __restrict__ out)
{
    extern __shared__ float sm[];
    float* xs    = sm;                       // [g][s][PITCH]; pros aliases [0,4352)
    float* vs    = xs + XS_F;                // [(g*4+n)][PITCH]
    float* psumb = vs + VS_F;                // [g][64]
    float* sbuf  = psumb + 128;              // part4 [2][8][16]f4 -> xsel [8][PITCH] -> loss [8]
    float* candv = sbuf + SBUF_F;            // [64]: [g][w][4]
    int*   candi = (int*)(candv + 64);       // [64]
    int*   isel  = candi + 64;               // [8]
    int*   psel  = isel + 8;                 // [8]
    __shared__ unsigned int amLast;

    float* xsel = sbuf;                      // alias (after psum combine done)
    float* pros = sm;                        // alias over xs[g=0] (after score phase)

    const int tid  = threadIdx.x;
    const int lane = tid & 31;
    const int w    = tid >> 5;               // 0..7
    const int b0   = blockIdx.x * G_PER_BLK;

    // coords for (n, h)-style phases
    const int cn = tid >> 6;          // 0..3
    const int ch = tid & 63;          // 0..63
    // coords for score/d2 phases (n minor -> 4-way row multicast)
    const int sp = tid >> 2;          // s (score) or p (VQ), 0..63
    const int sn = tid & 3;

    // --- stage pos = x + pe AND accumulate psum partials in registers.
    //     pe loaded once per (s,h4), applied to both batches. ---
    float4 acc0 = make_float4(0.f, 0.f, 0.f, 0.f);
    float4 acc1 = make_float4(0.f, 0.f, 0.f, 0.f);
    {
        const float4* xb4 = reinterpret_cast<const float4*>(x + (size_t)b0 * S_DIM * H_DIM);
        const float4* pe4 = reinterpret_cast<const float4*>(g_pe);
#pragma unroll
        for (int j = 0; j < 4; ++j) {
            int i4 = j * 256 + tid;           // g=0 index; g=1 index = i4 + 1024
            int s  = (i4 >> 4) & 63;
            int h4 = i4 & 15;
            float4 pv  = pe4[i4];             // shared by both batches
            float4 xv0 = xb4[i4];
            float4 xv1 = xb4[1024 + i4];
            float4 o0, o1;
            o0.x = xv0.x + pv.x; o0.y = xv0.y + pv.y;
            o0.z = xv0.z + pv.z; o0.w = xv0.w + pv.w;
            o1.x = xv1.x + pv.x; o1.y = xv1.y + pv.y;
            o1.z = xv1.z + pv.z; o1.w = xv1.w + pv.w;
            *reinterpret_cast<float4*>(&xs[(0 * 64 + s) * PITCH + h4 * 4]) = o0;
            *reinterpret_cast<float4*>(&xs[(1 * 64 + s) * PITCH + h4 * 4]) = o1;
            acc0.x += o0.x; acc0.y += o0.y; acc0.z += o0.z; acc0.w += o0.w;
            acc1.x += o1.x; acc1.y += o1.y; acc1.z += o1.z; acc1.w += o1.w;
        }
    }
    // pair-reduce: tid and tid^16 share (g span, h4); both get the pair sum
    acc0.x += __shfl_xor_sync(0xFFFFFFFFu, acc0.x, 16);
    acc0.y += __shfl_xor_sync(0xFFFFFFFFu, acc0.y, 16);
    acc0.z += __shfl_xor_sync(0xFFFFFFFFu, acc0.z, 16);
    acc0.w += __shfl_xor_sync(0xFFFFFFFFu, acc0.w, 16);
    acc1.x += __shfl_xor_sync(0xFFFFFFFFu, acc1.x, 16);
    acc1.y += __shfl_xor_sync(0xFFFFFFFFu, acc1.y, 16);
    acc1.z += __shfl_xor_sync(0xFFFFFFFFu, acc1.z, 16);
    acc1.w += __shfl_xor_sync(0xFFFFFFFFu, acc1.w, 16);
    if (lane < 16) {
        float4* p4 = reinterpret_cast<float4*>(sbuf);
        p4[(0 * 8 + w) * 16 + lane] = acc0;   // [g][w][h4]
        p4[(1 * 8 + w) * 16 + lane] = acc1;
    }

    __syncthreads();

    // --- psum combine: psumb[g*64+h] = sum_w sbuf[g*512 + w*64 + h] ---
    if (tid < 128) {
        int g = tid >> 6, h = tid & 63;
        const float* pb = sbuf + g * 512 + h;
        float s = 0.f;
#pragma unroll
        for (int wb = 0; wb < 8; ++wb)
            s += pb[wb * 64];
        psumb[tid] = s;
    }
    __syncthreads();

    // --- v[g][n][h]: M loaded ONCE, both batches accumulated ---
    {
        const float* Mt = g_M + ((size_t)cn * 64) * 64 + ch;   // stride 64 per k
        float a0 = 0.f, a1 = 0.f;
#pragma unroll 8
        for (int j = 0; j < 16; ++j) {
            float m0 = Mt[(j * 4 + 0) * 64];
            float m1 = Mt[(j * 4 + 1) * 64];
            float m2 = Mt[(j * 4 + 2) * 64];
            float m3 = Mt[(j * 4 + 3) * 64];
            float4 p0 = *reinterpret_cast<const float4*>(&psumb[ 0 + j * 4]);
            float4 p1 = *reinterpret_cast<const float4*>(&psumb[64 + j * 4]);
            a0 += m0 * p0.x + m1 * p0.y + m2 * p0.z + m3 * p0.w;
            a1 += m0 * p1.x + m1 * p1.y + m2 * p1.z + m3 * p1.w;
        }
        vs[(0 * 4 + cn) * PITCH + ch] = a0 * (1.0f / 512.0f);
        vs[(1 * 4 + cn) * PITCH + ch] = a1 * (1.0f / 512.0f);
    }
    __syncthreads();

    // --- score[g][n][s] = pos[g][s] . v[g][n] + gumbel; per-g warp argmax.
    //     gumbel computed lazily here (pure ALU) to keep reg pressure low. ---
#pragma unroll
    for (int g = 0; g < 2; ++g) {
        const float4* pr4 = reinterpret_cast<const float4*>(&xs[(g * 64 + sp) * PITCH]);
        const float4* vr4 = reinterpret_cast<const float4*>(&vs[(g * 4 + sn) * PITCH]);
        float lg = 0.f;
#pragma unroll
        for (int h4 = 0; h4 < 16; ++h4) {
            float4 a = pr4[h4], v = vr4[h4];
            lg += a.x * v.x + a.y * v.y + a.z * v.z + a.w * v.w;
        }
        float v = lg + gumbel_at((uint32_t)(b0 + g) * 256u + (uint32_t)sn * 64u + (uint32_t)sp);
        int idx = sp;
#pragma unroll
        for (int off = 4; off <= 16; off <<= 1) {
            float ov = __shfl_xor_sync(0xFFFFFFFFu, v, off);
            int   oi = __shfl_xor_sync(0xFFFFFFFFu, idx, off);
            if (ov > v || (ov == v && oi < idx)) { v = ov; idx = oi; }
        }
        if (lane < 4) { candv[g * 32 + w * 4 + lane] = v; candi[g * 32 + w * 4 + lane] = idx; }
    }
    __syncthreads();    // all xs reads complete -> xs[g=0] region reusable

    // --- stage prototypes into the dead xs region (overlaps argmax combine) ---
    {
        const float4* pp4 = reinterpret_cast<const float4*>(prototypes);
#pragma unroll
        for (int j = 0; j < 4; ++j) {
            int i4 = j * 256 + tid;
            int p  = i4 >> 4;
            int k4 = i4 & 15;
            *reinterpret_cast<float4*>(&pros[p * PITCH + k4 * 4]) = pp4[i4];
        }
    }
    if (tid < 8) {      // combine 8 warps per (g,n), first-max (warps ascend in s)
        int g = tid >> 2, n = tid & 3;
        float best = candv[g * 32 + n];
        int   bi   = candi[g * 32 + n];
        for (int wb = 1; wb < 8; ++wb) {
            float v = candv[g * 32 + wb * 4 + n];
            int   i = candi[g * 32 + wb * 4 + n];
            if (v > best || (v == best && i < bi)) { best = v; bi = i; }
        }
        isel[tid] = bi;
        out[OFF_IDX + (size_t)(b0 + g) * N_SEL + n] = (float)bi;
    }
    __syncthreads();

    // --- gather selected raw x rows (sbuf now reused as xsel) ---
#pragma unroll
    for (int g = 0; g < 2; ++g)
        xsel[(g * 4 + cn) * PITCH + ch] =
            x[((size_t)(b0 + g) * S_DIM + isel[g * 4 + cn]) * H_DIM + ch];
    __syncthreads();

    // --- VQ: pros row loaded ONCE, distances for both batches ---
    {
        const float4* prow4 = reinterpret_cast<const float4*>(&pros[sp * PITCH]);
        const float4* x0 = reinterpret_cast<const float4*>(&xsel[(0 * 4 + sn) * PITCH]);
        const float4* x1 = reinterpret_cast<const float4*>(&xsel[(1 * 4 + sn) * PITCH]);
        float d0 = 0.f, d1 = 0.f;
#pragma unroll
        for (int k4 = 0; k4 < 16; ++k4) {
            float4 pv = prow4[k4], a = x0[k4], b = x1[k4];
            d0 += pv.x * (pv.x - 2.0f * a.x);
            d0 += pv.y * (pv.y - 2.0f * a.y);
            d0 += pv.z * (pv.z - 2.0f * a.z);
            d0 += pv.w * (pv.w - 2.0f * a.w);
            d1 += pv.x * (pv.x - 2.0f * b.x);
            d1 += pv.y * (pv.y - 2.0f * b.y);
            d1 += pv.z * (pv.z - 2.0f * b.z);
            d1 += pv.w * (pv.w - 2.0f * b.w);
        }
#pragma unroll
        for (int g = 0; g < 2; ++g) {
            float v = g ? d1 : d0;
            int idx = sp;
#pragma unroll
            for (int off = 4; off <= 16; off <<= 1) {
                float ov = __shfl_xor_sync(0xFFFFFFFFu, v, off);
                int   oi = __shfl_xor_sync(0xFFFFFFFFu, idx, off);
                if (ov < v || (ov == v && oi < idx)) { v = ov; idx = oi; }
            }
            if (lane < 4) { candv[g * 32 + w * 4 + lane] = v; candi[g * 32 + w * 4 + lane] = idx; }
        }
    }
    __syncthreads();
    if (tid < 8) {      // combine, first-min
        int g = tid >> 2, n = tid & 3;
        float best = candv[g * 32 + n];
        int   bi   = candi[g * 32 + n];
        for (int wb = 1; wb < 8; ++wb) {
            float v = candv[g * 32 + wb * 4 + n];
            int   i = candi[g * 32 + wb * 4 + n];
            if (v < best || (v == best && i < bi)) { best = v; bi = i; }
        }
        psel[tid] = bi;
    }
    __syncthreads();

    // --- outputs (reference rounding preserved) + loss contribution ---
    float losspart = 0.f;
#pragma unroll
    for (int g = 0; g < 2; ++g) {
        float xv  = xsel[(g * 4 + cn) * PITCH + ch];
        float pv  = pros[psel[g * 4 + cn] * PITCH + ch];
        float d   = pv - xv;
        float pst = xv + d;
        size_t ob = (size_t)(b0 + g) * 256 + (size_t)tid;
        out[ob]           = pst;
        out[OFF_RES + ob] = xv - pst;
        losspart += d * d;
    }
    __syncthreads();   // all xsel reads done before sbuf is reused for loss

    // --- deterministic loss reduction (warp shuffle + smem combine) ---
    {
        float v = losspart;
#pragma unroll
        for (int off = 16; off > 0; off >>= 1)
            v += __shfl_xor_sync(0xFFFFFFFFu, v, off);
        if (lane == 0) sbuf[w] = v;
    }
    __syncthreads();
    if (tid < 32) {
        float v = (tid < 8) ? sbuf[tid] : 0.f;
#pragma unroll
        for (int off = 16; off > 0; off >>= 1)
            v += __shfl_xor_sync(0xFFFFFFFFu, v, off);
        if (tid == 0) g_partial[blockIdx.x] = v;
    }

    // --- fused loss finalize: last block sums 2048 partials in fixed order ---
    __threadfence();
    if (tid == 0)
        amLast = (atomicAdd(&g_count, 1u) == (unsigned)(NBLKS - 1)) ? 1u : 0u;
    __syncthreads();
    if (amLast) {
        __threadfence();
        float v = 0.f;
#pragma unroll
        for (int j = 0; j < 8; ++j)             // fixed order -> deterministic
            v += g_partial[j * 256 + tid];
#pragma unroll
        for (int off = 16; off > 0; off >>= 1)
            v += __shfl_xor_sync(0xFFFFFFFFu, v, off);
        if (lane == 0) sbuf[w] = v;
        __syncthreads();
        if (tid < 32) {
            float s = (tid < 8) ? sbuf[tid] : 0.f;
#pragma unroll
            for (int off = 16; off > 0; off >>= 1)
                s += __shfl_xor_sync(0xFFFFFFFFu, s, off);
            if (tid == 0) {
                out[OFF_LOSS] = s * 1.25f / (float)(B_TOT * N_SEL * H_DIM);
                g_count = 0;            // reset for next graph replay
            }
        }
    }
}

// ---------------------------------------------------------------------------
extern "C" void kernel_launch(void* const* d_in, const int* in_sizes, int n_in,
                              void* d_out, int out_size) {
    (void)in_sizes; (void)n_in; (void)out_size;
    const float* x  = (const float*)d_in[0];
    const float* Wq = (const float*)d_in[1];
    const float* Wk = (const float*)d_in[2];
    const float* pr = (const float*)d_in[3];
    float* out = (float*)d_out;

    cudaFuncSetAttribute(main_kernel,
                         cudaFuncAttributeMaxDynamicSharedMemorySize, SMEM_BYTES);

    prep_kernel<<<260, 256>>>(Wq, Wk);
    main_kernel<<<NBLKS, THREADS, SMEM_BYTES>>>(x, pr, out);
}